// round 2
// baseline (speedup 1.0000x reference)
#include <cuda_runtime.h>
#include <math.h>

#define HW 128
#define C_MID 64
#define C_IN 67            // 64 lidar + hm + hmf + ones
#define MAXB 8

// ---------------- scratch (no allocs allowed) ----------------
__device__ float g_hm [MAXB * HW * HW];
__device__ float g_hmf[MAXB * HW * HW];
__device__ float g_wf [C_IN * 9 * 64];   // folded weights, layout [c][k][o]
__device__ int   g_coor64;

// ---------------- int64-vs-int32 rcoors detection ----------------
__global__ void detect_kernel(const int* rc_as_i32) {
    if (threadIdx.x == 0 && blockIdx.x == 0) {
        int all0 = 1;
        #pragma unroll 1
        for (int i = 1; i < 128; i += 2) all0 &= (rc_as_i32[i] == 0);
        g_coor64 = all0;   // 1 => int64 layout, 0 => int32
    }
}

// ---------------- zero heatmap buffers ----------------
__global__ void init_kernel(int n) {
    int i = blockIdx.x * blockDim.x + threadIdx.x;
    if (i < n) { g_hm[i] = 0.0f; g_hmf[i] = 0.0f; }
}

// ---------------- fold att conv into comp conv ----------------
// g_wf[c][k][o]: c<64 -> comp_w[o][c][k]; c=64/65/66 -> sum_c2 comp_w[o][64+c2][k]*{att_w0,att_w1,att_b}
__global__ void fold_kernel(const float* __restrict__ comp_w,
                            const float* __restrict__ att_w,
                            const float* __restrict__ att_b) {
    int t = blockIdx.x * blockDim.x + threadIdx.x;
    if (t >= 64 * 9) return;
    int o = t / 9, k = t % 9;
    #pragma unroll 1
    for (int c = 0; c < 64; c++)
        g_wf[(c * 9 + k) * 64 + o] = comp_w[(o * 128 + c) * 9 + k];
    float s0 = 0.f, s1 = 0.f, s2 = 0.f;
    #pragma unroll 1
    for (int c = 0; c < 64; c++) {
        float w = comp_w[(o * 128 + 64 + c) * 9 + k];
        s0 += w * att_w[2 * c];
        s1 += w * att_w[2 * c + 1];
        s2 += w * att_b[c];
    }
    g_wf[(64 * 9 + k) * 64 + o] = s0;
    g_wf[(65 * 9 + k) * 64 + o] = s1;
    g_wf[(66 * 9 + k) * 64 + o] = s2;
}

// ---------------- gaussian splat with atomicMax ----------------
__global__ void draw_kernel(const void* __restrict__ rcoors,
                            const float* __restrict__ rcs,
                            const float* __restrict__ gamma_p,
                            int N) {
    int p = blockIdx.x;
    if (p >= N) return;
    int is64 = g_coor64;
    int b, y, x;
    if (is64) {
        const long long* r8 = (const long long*)rcoors;
        b = (int)r8[p * 4 + 0]; y = (int)r8[p * 4 + 2]; x = (int)r8[p * 4 + 3];
    } else {
        const int* r4 = (const int*)rcoors;
        b = r4[p * 4 + 0]; y = r4[p * 4 + 2]; x = r4[p * 4 + 3];
    }
    float t = fmaxf(rcs[p], 0.0f);
    float gamma = *gamma_p;
    float r = floorf(gamma * t + 1.0f);
    float sigma = (2.0f * r + 1.0f) / 6.0f;
    float inv2s2 = 1.0f / (2.0f * sigma * sigma);
    int ri = (int)r;
    if (ri > HW) ri = HW;                 // safety clamp
    int side = 2 * ri + 1;
    int tot = side * side;
    const float EPS = 1.1920929e-7f;      // finfo(f32).eps
    for (int idx = threadIdx.x; idx < tot; idx += blockDim.x) {
        int dy = idx / side - ri;
        int dx = idx % side - ri;
        int py = y + dy, px = x + dx;
        if ((unsigned)py < HW && (unsigned)px < HW) {
            float d2 = (float)(dy * dy + dx * dx);
            float g = __expf(-d2 * inv2s2) ; // fast exp deviates; use precise:
            g = expf(-d2 * inv2s2);
            if (g >= EPS) {
                int off = b * (HW * HW) + py * HW + px;
                atomicMax((int*)&g_hm[off],  __float_as_int(g));
                atomicMax((int*)&g_hmf[off], __float_as_int(g * t));
            }
        }
    }
}

// ---------------- main 3x3 conv over 67 channels ----------------
// block: 32 out-ch (blockIdx.y selects half) x 16x16 tile (blockIdx.x) x batch (blockIdx.z)
// thread: 4 pixels (consecutive x) x 8 out-ch -> 32 accumulators
#define IN_STRIDE 19
#define IN_CH_WORDS (18 * IN_STRIDE)          // 342
#define S_IN_WORDS  (C_IN * IN_CH_WORDS)      // 22914
#define S_IN_PAD    22916                     // 16B-align weight region
#define S_W_WORDS   (C_IN * 9 * 32)           // 19296
#define SMEM_WORDS  (S_IN_PAD + S_W_WORDS)
#define SMEM_BYTES  (SMEM_WORDS * 4)

__global__ void __launch_bounds__(256, 1)
conv_kernel(const float* __restrict__ lidar,
            const float* __restrict__ comp_b,
            float* __restrict__ out, int B) {
    extern __shared__ float smem[];
    float* s_in = smem;
    float* s_w  = smem + S_IN_PAD;

    const int b    = blockIdx.z;
    const int og   = blockIdx.y;                 // 0..1 : which 32 out channels
    const int tile = blockIdx.x;                 // 0..63
    const int ty0  = (tile >> 3) << 4;
    const int tx0  = (tile & 7) << 4;
    const int tid  = threadIdx.x;

    // ---- load weights: s_w[(c*9+k)*32 + o'] = g_wf[(c*9+k)*64 + og*32 + o'] ----
    #pragma unroll 1
    for (int i = tid; i < S_W_WORDS; i += 256) {
        int ck = i >> 5;
        int op = i & 31;
        s_w[i] = g_wf[ck * 64 + og * 32 + op];
    }

    // ---- load input tile (with halo, zero-padded), 67 channels ----
    const float* lid_b = lidar + (size_t)b * C_MID * HW * HW;
    const float* hm_b  = g_hm  + b * HW * HW;
    const float* hmf_b = g_hmf + b * HW * HW;
    #pragma unroll 1
    for (int i = tid; i < C_IN * 324; i += 256) {
        int c   = i / 324;
        int rem = i - c * 324;
        int iy  = rem / 18;
        int ix  = rem - iy * 18;
        int y   = ty0 + iy - 1;
        int x   = tx0 + ix - 1;
        float v = 0.0f;
        if ((unsigned)y < HW && (unsigned)x < HW) {
            int sp = y * HW + x;
            if (c < C_MID)      v = lid_b[c * HW * HW + sp];
            else if (c == 64)   v = hm_b[sp];
            else if (c == 65)   v = hmf_b[sp];
            else                v = 1.0f;
        }
        s_in[c * IN_CH_WORDS + iy * IN_STRIDE + ix] = v;
    }
    __syncthreads();

    // ---- thread micro-tile ----
    const int ot  = tid >> 6;          // 0..3 : 8-out-ch subgroup (warp-uniform)
    const int pg  = tid & 63;
    const int row = pg >> 2;           // 0..15
    const int xb  = (pg & 3) << 2;     // 0,4,8,12

    float acc[4][8];
    #pragma unroll
    for (int i = 0; i < 8; i++) {
        float bv = comp_b[og * 32 + ot * 8 + i];
        #pragma unroll
        for (int p = 0; p < 4; p++) acc[p][i] = bv;
    }

    #pragma unroll 1
    for (int c = 0; c < C_IN; c++) {
        const float* ip = s_in + c * IN_CH_WORDS;
        #pragma unroll
        for (int ky = 0; ky < 3; ky++) {
            const float* rp = ip + (row + ky) * IN_STRIDE + xb;
            float v[6];
            #pragma unroll
            for (int j = 0; j < 6; j++) v[j] = rp[j];
            #pragma unroll
            for (int kx = 0; kx < 3; kx++) {
                const float4* wp = reinterpret_cast<const float4*>(
                    s_w + ((c * 9 + ky * 3 + kx) * 32 + ot * 8));
                float4 wa = wp[0], wb = wp[1];
                float w[8] = {wa.x, wa.y, wa.z, wa.w, wb.x, wb.y, wb.z, wb.w};
                #pragma unroll
                for (int p = 0; p < 4; p++) {
                    float vv = v[p + kx];
                    #pragma unroll
                    for (int i = 0; i < 8; i++)
                        acc[p][i] = fmaf(vv, w[i], acc[p][i]);
                }
            }
        }
    }

    // ---- store: 8 x STG.128 ----
    #pragma unroll
    for (int i = 0; i < 8; i++) {
        int o = og * 32 + ot * 8 + i;
        float* op = out + (((size_t)b * 64 + o) * HW + (ty0 + row)) * HW + tx0 + xb;
        float4 st = make_float4(acc[0][i], acc[1][i], acc[2][i], acc[3][i]);
        *reinterpret_cast<float4*>(op) = st;
    }
}

// ---------------- launch ----------------
extern "C" void kernel_launch(void* const* d_in, const int* in_sizes, int n_in,
                              void* d_out, int out_size) {
    const float* lidar  = (const float*)d_in[0];
    // d_in[1] voxels_feat_radar: unused by reference
    const void*  rcoors = d_in[2];
    // d_in[3] batch_size: derived from sizes instead
    const float* rcs    = (const float*)d_in[4];
    const float* gamma  = (const float*)d_in[5];
    const float* att_w  = (const float*)d_in[6];
    const float* att_b  = (const float*)d_in[7];
    const float* comp_w = (const float*)d_in[8];
    const float* comp_b = (const float*)d_in[9];
    float* out = (float*)d_out;

    int B = in_sizes[0] / (C_MID * HW * HW);
    if (B < 1) B = 1; if (B > MAXB) B = MAXB;
    int N = in_sizes[4];

    detect_kernel<<<1, 32>>>((const int*)rcoors);

    int nz = B * HW * HW;
    init_kernel<<<(nz + 255) / 256, 256>>>(nz);

    fold_kernel<<<3, 256>>>(comp_w, att_w, att_b);

    draw_kernel<<<N, 128>>>(rcoors, rcs, gamma, N);

    cudaFuncSetAttribute(conv_kernel,
                         cudaFuncAttributeMaxDynamicSharedMemorySize, SMEM_BYTES);
    dim3 grid(64, 2, B);
    conv_kernel<<<grid, 256, SMEM_BYTES>>>(lidar, comp_b, out, B);
}

// round 5
// speedup vs baseline: 1.9880x; 1.9880x over previous
#include <cuda_runtime.h>
#include <cuda_bf16.h>
#include <math.h>
#include <stdint.h>

#define HW 128
#define C_MID 64
#define MAXB 8

// ---------------- scratch (no allocs allowed) ----------------
__device__ float g_hm [MAXB * HW * HW];
__device__ float g_hmf[MAXB * HW * HW];
// main weights, ldmatrix layout: [tap][nb(8)][k(64)][no(8)] bf16, hi & lo
__device__ __align__(16) __nv_bfloat16 g_wmh[9 * 8 * 64 * 8];
__device__ __align__(16) __nv_bfloat16 g_wml[9 * 8 * 64 * 8];
// extra-channel weights: [nb(8)][slot(32)][no(8)] bf16, hi & lo
__device__ __align__(16) __nv_bfloat16 g_weh[8 * 32 * 8];
__device__ __align__(16) __nv_bfloat16 g_wel[8 * 32 * 8];
__device__ int g_coor64;

// ---------------- helpers ----------------
__device__ __forceinline__ uint32_t smem_u32(const void* p) {
    uint32_t a;
    asm("{ .reg .u64 t; cvta.to.shared.u64 t, %1; cvt.u32.u64 %0, t; }" : "=r"(a) : "l"(p));
    return a;
}

__device__ __forceinline__ void ldsm_x4(uint32_t addr, uint32_t& r0, uint32_t& r1,
                                        uint32_t& r2, uint32_t& r3) {
    asm volatile("ldmatrix.sync.aligned.m8n8.x4.shared.b16 {%0,%1,%2,%3}, [%4];"
                 : "=r"(r0), "=r"(r1), "=r"(r2), "=r"(r3) : "r"(addr));
}
__device__ __forceinline__ void ldsm_x4_t(uint32_t addr, uint32_t& r0, uint32_t& r1,
                                          uint32_t& r2, uint32_t& r3) {
    asm volatile("ldmatrix.sync.aligned.m8n8.x4.trans.shared.b16 {%0,%1,%2,%3}, [%4];"
                 : "=r"(r0), "=r"(r1), "=r"(r2), "=r"(r3) : "r"(addr));
}
__device__ __forceinline__ void mma_bf16(float* d, const uint32_t* a,
                                         uint32_t b0, uint32_t b1) {
    asm volatile(
        "mma.sync.aligned.m16n8k16.row.col.f32.bf16.bf16.f32 "
        "{%0,%1,%2,%3},{%4,%5,%6,%7},{%8,%9},{%0,%1,%2,%3};"
        : "+f"(d[0]), "+f"(d[1]), "+f"(d[2]), "+f"(d[3])
        : "r"(a[0]), "r"(a[1]), "r"(a[2]), "r"(a[3]), "r"(b0), "r"(b1));
}

__device__ __forceinline__ uint32_t pack_hl(float v0, float v1, uint32_t& lo) {
    __nv_bfloat16 h0 = __float2bfloat16(v0);
    __nv_bfloat16 h1 = __float2bfloat16(v1);
    __nv_bfloat16 l0 = __float2bfloat16(v0 - __bfloat162float(h0));
    __nv_bfloat16 l1 = __float2bfloat16(v1 - __bfloat162float(h1));
    lo = (uint32_t)__bfloat16_as_ushort(l0) | ((uint32_t)__bfloat16_as_ushort(l1) << 16);
    return (uint32_t)__bfloat16_as_ushort(h0) | ((uint32_t)__bfloat16_as_ushort(h1) << 16);
}

// ---------------- int64-vs-int32 rcoors detection ----------------
__global__ void detect_kernel(const int* rc_as_i32) {
    if (threadIdx.x == 0 && blockIdx.x == 0) {
        int all0 = 1;
        #pragma unroll 1
        for (int i = 1; i < 128; i += 2) all0 &= (rc_as_i32[i] == 0);
        g_coor64 = all0;
    }
}

// ---------------- zero heatmap buffers ----------------
__global__ void init_kernel(int n) {
    int i = blockIdx.x * blockDim.x + threadIdx.x;
    if (i < n) { g_hm[i] = 0.0f; g_hmf[i] = 0.0f; }
}

// ---------------- fold weights into ldmatrix layouts ----------------
__global__ void fold_kernel(const float* __restrict__ comp_w,
                            const float* __restrict__ att_w,
                            const float* __restrict__ att_b) {
    int t = blockIdx.x * blockDim.x + threadIdx.x;
    if (t >= 64 * 9) return;
    int o = t / 9, tap = t % 9;
    int nb = o >> 3, no = o & 7;
    #pragma unroll 1
    for (int c = 0; c < 64; c++) {
        float w = comp_w[(o * 128 + c) * 9 + tap];
        __nv_bfloat16 h = __float2bfloat16(w);
        __nv_bfloat16 l = __float2bfloat16(w - __bfloat162float(h));
        int idx = ((tap * 8 + nb) * 64 + c) * 8 + no;
        g_wmh[idx] = h;
        g_wml[idx] = l;
    }
    float s0 = 0.f, s1 = 0.f, s2 = 0.f;
    #pragma unroll 1
    for (int c = 0; c < 64; c++) {
        float w = comp_w[(o * 128 + 64 + c) * 9 + tap];
        s0 += w * att_w[2 * c];
        s1 += w * att_w[2 * c + 1];
        s2 += w * att_b[c];
    }
    float sv[3] = {s0, s1, s2};
    #pragma unroll
    for (int j = 0; j < 3; j++) {
        int slot = tap * 3 + j;
        __nv_bfloat16 h = __float2bfloat16(sv[j]);
        __nv_bfloat16 l = __float2bfloat16(sv[j] - __bfloat162float(h));
        int idx = (nb * 32 + slot) * 8 + no;
        g_weh[idx] = h;
        g_wel[idx] = l;
    }
    if (tap == 0) {
        for (int s = 27; s < 32; s++) {
            int idx = (nb * 32 + s) * 8 + no;
            g_weh[idx] = __float2bfloat16(0.f);
            g_wel[idx] = __float2bfloat16(0.f);
        }
    }
}

// ---------------- gaussian splat with atomicMax ----------------
__global__ void draw_kernel(const void* __restrict__ rcoors,
                            const float* __restrict__ rcs,
                            const float* __restrict__ gamma_p,
                            int N) {
    int p = blockIdx.x;
    if (p >= N) return;
    int is64 = g_coor64;
    int b, y, x;
    if (is64) {
        const long long* r8 = (const long long*)rcoors;
        b = (int)r8[p * 4 + 0]; y = (int)r8[p * 4 + 2]; x = (int)r8[p * 4 + 3];
    } else {
        const int* r4 = (const int*)rcoors;
        b = r4[p * 4 + 0]; y = r4[p * 4 + 2]; x = r4[p * 4 + 3];
    }
    float t = fmaxf(rcs[p], 0.0f);
    float gamma = *gamma_p;
    float r = floorf(gamma * t + 1.0f);
    float sigma = (2.0f * r + 1.0f) / 6.0f;
    float inv2s2 = 1.0f / (2.0f * sigma * sigma);
    int ri = (int)r;
    if (ri > HW) ri = HW;
    int side = 2 * ri + 1;
    int tot = side * side;
    const float EPS = 1.1920929e-7f;
    for (int idx = threadIdx.x; idx < tot; idx += blockDim.x) {
        int dy = idx / side - ri;
        int dx = idx % side - ri;
        int py = y + dy, px = x + dx;
        if ((unsigned)py < HW && (unsigned)px < HW) {
            float d2 = (float)(dy * dy + dx * dx);
            float g = expf(-d2 * inv2s2);
            if (g >= EPS) {
                int off = b * (HW * HW) + py * HW + px;
                atomicMax((int*)&g_hm[off],  __float_as_int(g));
                atomicMax((int*)&g_hmf[off], __float_as_int(g * t));
            }
        }
    }
}

// ---------------- mma.sync conv ----------------
// CTA = one output row y, all 64 oc, 128 px. 8 warps; warp w: px [16w,16w+16) x 64 oc.
// Row buffer [130 rows][64 ch] bf16, stride 144B (conflict-free ldmatrix), rows 0/129 zero.
// kx shift = row offset. Weights [tap][nb][k][8oc], ldmatrix.x4.trans.
#define SM_WMH 0
#define SM_WML 73728
#define SM_WEH 147456
#define SM_WEL 151552
#define SM_RBH 155648
#define SM_RBL 174368
#define SM_EAH 193088
#define SM_EAL 203328
#define SMEM_TOTAL 213568
#define RB_STRIDE 144
#define EA_STRIDE 80

__global__ void __launch_bounds__(256, 1)
conv_mma_kernel(const float* __restrict__ lidar,
                const float* __restrict__ comp_b,
                float* __restrict__ out) {
    extern __shared__ char smc[];
    uint32_t sb = smem_u32(smc);
    const int tid  = threadIdx.x;
    const int wid  = tid >> 5;
    const int lane = tid & 31;
    const int y = blockIdx.x;
    const int b = blockIdx.y;

    // ---- copy weights to smem (uint4) ----
    {
        const uint4* s0 = (const uint4*)g_wmh; uint4* d0 = (uint4*)(smc + SM_WMH);
        const uint4* s1 = (const uint4*)g_wml; uint4* d1 = (uint4*)(smc + SM_WML);
        #pragma unroll 1
        for (int i = tid; i < 4608; i += 256) { d0[i] = s0[i]; d1[i] = s1[i]; }
        const uint4* s2 = (const uint4*)g_weh; uint4* d2 = (uint4*)(smc + SM_WEH);
        const uint4* s3 = (const uint4*)g_wel; uint4* d3 = (uint4*)(smc + SM_WEL);
        #pragma unroll 1
        for (int i = tid; i < 256; i += 256) { d2[i] = s2[i]; d3[i] = s3[i]; }
    }

    // ---- zero guard rows 0 and 129 of row buffers ----
    if (tid < 72) {
        int r = (tid < 36) ? 0 : 129;
        int w = (tid < 36) ? tid : tid - 36;
        *(uint32_t*)(smc + SM_RBH + r * RB_STRIDE + w * 4) = 0;
        *(uint32_t*)(smc + SM_RBL + r * RB_STRIDE + w * 4) = 0;
    }

    // ---- build extra-channel A: [128 px][32 slots] hi/lo ----
    const float* hm_b  = g_hm  + b * HW * HW;
    const float* hmf_b = g_hmf + b * HW * HW;
    #pragma unroll 1
    for (int i = tid; i < 2048; i += 256) {
        int px = i & 127;
        int sp = i >> 7;                 // slot pair 0..15
        float v[2];
        #pragma unroll
        for (int u = 0; u < 2; u++) {
            int slot = sp * 2 + u;
            float val = 0.f;
            if (slot < 27) {
                int tap = slot / 3, j = slot - 3 * tap;
                int kyy = tap / 3, kxx = tap - 3 * kyy;
                int ry = y + kyy - 1, rx = px + kxx - 1;
                if ((unsigned)ry < HW && (unsigned)rx < HW) {
                    if (j == 0)      val = hm_b[ry * HW + rx];
                    else if (j == 1) val = hmf_b[ry * HW + rx];
                    else             val = 1.0f;
                }
            }
            v[u] = val;
        }
        uint32_t lp, hp = pack_hl(v[0], v[1], lp);
        *(uint32_t*)(smc + SM_EAH + px * EA_STRIDE + sp * 4) = hp;
        *(uint32_t*)(smc + SM_EAL + px * EA_STRIDE + sp * 4) = lp;
    }

    // ---- accumulators: 8 n-tiles of m16n8 ----
    float acc[8][4];
    #pragma unroll
    for (int t = 0; t < 8; t++)
        #pragma unroll
        for (int j = 0; j < 4; j++) acc[t][j] = 0.f;

    const int px0 = wid * 16;
    const uint32_t row_add = (lane & 7) + ((lane >> 3) & 1) * 8;  // 0..15
    const uint32_t a_half  = (lane >> 4) * 16;                    // 0 / 16B
    const uint32_t b_kidx  = lane & 15;
    const uint32_t b_nbadd = (lane >> 4);                         // 0 / 1

    const float* lid_b = lidar + (size_t)b * C_MID * HW * HW;

    for (int ky = 0; ky < 3; ky++) {
        int ry = y + ky - 1;
        int valid = ((unsigned)ry < HW);
        __syncthreads();
        if (valid) {
            const float* rp = lid_b + (size_t)ry * HW;
            #pragma unroll 1
            for (int i = tid; i < 4096; i += 256) {
                int px = i & 127;
                int cp = i >> 7;                 // channel pair 0..31
                float v0 = rp[(size_t)(2 * cp) * (HW * HW) + px];
                float v1 = rp[(size_t)(2 * cp + 1) * (HW * HW) + px];
                uint32_t lp, hp = pack_hl(v0, v1, lp);
                *(uint32_t*)(smc + SM_RBH + (px + 1) * RB_STRIDE + cp * 4) = hp;
                *(uint32_t*)(smc + SM_RBL + (px + 1) * RB_STRIDE + cp * 4) = lp;
            }
        }
        __syncthreads();
        if (!valid) continue;

        #pragma unroll 1
        for (int kx = 0; kx < 3; kx++) {
            int tap = ky * 3 + kx;
            uint32_t aH = sb + SM_RBH + (px0 + kx + row_add) * RB_STRIDE + a_half;
            uint32_t aL = aH + (SM_RBL - SM_RBH);
            uint32_t wB = sb + SM_WMH + ((tap * 8 + b_nbadd) * 64 + b_kidx) * 16;
            #pragma unroll
            for (int kc = 0; kc < 4; kc++) {
                uint32_t Ah[4], Al[4];
                ldsm_x4(aH + kc * 32, Ah[0], Ah[1], Ah[2], Ah[3]);
                ldsm_x4(aL + kc * 32, Al[0], Al[1], Al[2], Al[3]);
                #pragma unroll
                for (int nbp = 0; nbp < 4; nbp++) {
                    uint32_t bh0, bh1, bh2, bh3, bl0, bl1, bl2, bl3;
                    uint32_t boff = nbp * 2048 + kc * 256;
                    ldsm_x4_t(wB + boff, bh0, bh1, bh2, bh3);
                    ldsm_x4_t(wB + boff + (SM_WML - SM_WMH), bl0, bl1, bl2, bl3);
                    mma_bf16(acc[2 * nbp],     Ah, bh0, bh1);
                    mma_bf16(acc[2 * nbp + 1], Ah, bh2, bh3);
                    mma_bf16(acc[2 * nbp],     Ah, bl0, bl1);
                    mma_bf16(acc[2 * nbp + 1], Ah, bl2, bl3);
                    mma_bf16(acc[2 * nbp],     Al, bh0, bh1);
                    mma_bf16(acc[2 * nbp + 1], Al, bh2, bh3);
                }
            }
        }
    }

    // ---- extra channels: K = 32 (2 k-chunks) ----
    {
        uint32_t aH = sb + SM_EAH + (px0 + row_add) * EA_STRIDE + a_half;
        uint32_t aL = aH + (SM_EAL - SM_EAH);
        uint32_t wB = sb + SM_WEH + (b_nbadd * 32 + b_kidx) * 16;
        #pragma unroll
        for (int kc = 0; kc < 2; kc++) {
            uint32_t Ah[4], Al[4];
            ldsm_x4(aH + kc * 32, Ah[0], Ah[1], Ah[2], Ah[3]);
            ldsm_x4(aL + kc * 32, Al[0], Al[1], Al[2], Al[3]);
            #pragma unroll
            for (int nbp = 0; nbp < 4; nbp++) {
                uint32_t bh0, bh1, bh2, bh3, bl0, bl1, bl2, bl3;
                uint32_t boff = nbp * 1024 + kc * 256;   // nb stride = 32*16 = 512
                ldsm_x4_t(wB + boff, bh0, bh1, bh2, bh3);
                ldsm_x4_t(wB + boff + (SM_WEL - SM_WEH), bl0, bl1, bl2, bl3);
                mma_bf16(acc[2 * nbp],     Ah, bh0, bh1);
                mma_bf16(acc[2 * nbp + 1], Ah, bh2, bh3);
                mma_bf16(acc[2 * nbp],     Ah, bl0, bl1);
                mma_bf16(acc[2 * nbp + 1], Ah, bl2, bl3);
                mma_bf16(acc[2 * nbp],     Al, bh0, bh1);
                mma_bf16(acc[2 * nbp + 1], Al, bh2, bh3);
            }
        }
    }

    // ---- epilogue: D fragment -> NCHW + bias ----
    {
        int r0 = px0 + (lane >> 2);
        #pragma unroll
        for (int nt = 0; nt < 8; nt++) {
            int oc = nt * 8 + (lane & 3) * 2;
            float bv0 = comp_b[oc], bv1 = comp_b[oc + 1];
            float* o0 = out + (((size_t)b * 64 + oc) * HW + y) * HW;
            float* o1 = o0 + (size_t)HW * HW;
            o0[r0]     = acc[nt][0] + bv0;
            o1[r0]     = acc[nt][1] + bv1;
            o0[r0 + 8] = acc[nt][2] + bv0;
            o1[r0 + 8] = acc[nt][3] + bv1;
        }
    }
}

// ---------------- launch ----------------
extern "C" void kernel_launch(void* const* d_in, const int* in_sizes, int n_in,
                              void* d_out, int out_size) {
    const float* lidar  = (const float*)d_in[0];
    const void*  rcoors = d_in[2];
    const float* rcs    = (const float*)d_in[4];
    const float* gamma  = (const float*)d_in[5];
    const float* att_w  = (const float*)d_in[6];
    const float* att_b  = (const float*)d_in[7];
    const float* comp_w = (const float*)d_in[8];
    const float* comp_b = (const float*)d_in[9];
    float* out = (float*)d_out;

    int B = in_sizes[0] / (C_MID * HW * HW);
    if (B < 1) B = 1; if (B > MAXB) B = MAXB;
    int N = in_sizes[4];

    detect_kernel<<<1, 32>>>((const int*)rcoors);

    int nz = B * HW * HW;
    init_kernel<<<(nz + 255) / 256, 256>>>(nz);

    fold_kernel<<<3, 256>>>(comp_w, att_w, att_b);

    draw_kernel<<<N, 128>>>(rcoors, rcs, gamma, N);

    cudaFuncSetAttribute(conv_mma_kernel,
                         cudaFuncAttributeMaxDynamicSharedMemorySize, SMEM_TOTAL);
    dim3 grid(HW, B);
    conv_mma_kernel<<<grid, 256, SMEM_TOTAL>>>(lidar, comp_b, out);
}

// round 6
// speedup vs baseline: 2.6720x; 1.3441x over previous
#include <cuda_runtime.h>
#include <cuda_bf16.h>
#include <math.h>
#include <stdint.h>

#define HW 128
#define C_MID 64
#define MAXB 8

// ---------------- scratch (no allocs allowed) ----------------
__device__ float g_hm [MAXB * HW * HW];
__device__ float g_hmf[MAXB * HW * HW];
// main weights, ldmatrix layout: [tap][nb(8)][k(64)][no(8)] bf16, hi & lo
__device__ __align__(16) __nv_bfloat16 g_wmh[9 * 8 * 64 * 8];
__device__ __align__(16) __nv_bfloat16 g_wml[9 * 8 * 64 * 8];
// extra-channel weights: [nb(8)][slot(32)][no(8)] bf16, hi & lo
__device__ __align__(16) __nv_bfloat16 g_weh[8 * 32 * 8];
__device__ __align__(16) __nv_bfloat16 g_wel[8 * 32 * 8];
__device__ int g_coor64;

// ---------------- helpers ----------------
__device__ __forceinline__ uint32_t smem_u32(const void* p) {
    uint32_t a;
    asm("{ .reg .u64 t; cvta.to.shared.u64 t, %1; cvt.u32.u64 %0, t; }" : "=r"(a) : "l"(p));
    return a;
}

__device__ __forceinline__ void ldsm_x4(uint32_t addr, uint32_t& r0, uint32_t& r1,
                                        uint32_t& r2, uint32_t& r3) {
    asm volatile("ldmatrix.sync.aligned.m8n8.x4.shared.b16 {%0,%1,%2,%3}, [%4];"
                 : "=r"(r0), "=r"(r1), "=r"(r2), "=r"(r3) : "r"(addr));
}
__device__ __forceinline__ void ldsm_x4_t(uint32_t addr, uint32_t& r0, uint32_t& r1,
                                          uint32_t& r2, uint32_t& r3) {
    asm volatile("ldmatrix.sync.aligned.m8n8.x4.trans.shared.b16 {%0,%1,%2,%3}, [%4];"
                 : "=r"(r0), "=r"(r1), "=r"(r2), "=r"(r3) : "r"(addr));
}
__device__ __forceinline__ void mma_bf16(float* d, const uint32_t* a,
                                         uint32_t b0, uint32_t b1) {
    asm volatile(
        "mma.sync.aligned.m16n8k16.row.col.f32.bf16.bf16.f32 "
        "{%0,%1,%2,%3},{%4,%5,%6,%7},{%8,%9},{%0,%1,%2,%3};"
        : "+f"(d[0]), "+f"(d[1]), "+f"(d[2]), "+f"(d[3])
        : "r"(a[0]), "r"(a[1]), "r"(a[2]), "r"(a[3]), "r"(b0), "r"(b1));
}

__device__ __forceinline__ uint32_t pack_hl(float v0, float v1, uint32_t& lo) {
    __nv_bfloat16 h0 = __float2bfloat16(v0);
    __nv_bfloat16 h1 = __float2bfloat16(v1);
    __nv_bfloat16 l0 = __float2bfloat16(v0 - __bfloat162float(h0));
    __nv_bfloat16 l1 = __float2bfloat16(v1 - __bfloat162float(h1));
    lo = (uint32_t)__bfloat16_as_ushort(l0) | ((uint32_t)__bfloat16_as_ushort(l1) << 16);
    return (uint32_t)__bfloat16_as_ushort(h0) | ((uint32_t)__bfloat16_as_ushort(h1) << 16);
}

// ---------------- int64-vs-int32 rcoors detection ----------------
__global__ void detect_kernel(const int* rc_as_i32) {
    if (threadIdx.x == 0 && blockIdx.x == 0) {
        int all0 = 1;
        #pragma unroll 1
        for (int i = 1; i < 128; i += 2) all0 &= (rc_as_i32[i] == 0);
        g_coor64 = all0;
    }
}

// ---------------- zero heatmap buffers ----------------
__global__ void init_kernel(int n) {
    int i = blockIdx.x * blockDim.x + threadIdx.x;
    if (i < n) { g_hm[i] = 0.0f; g_hmf[i] = 0.0f; }
}

// ---------------- fold weights into ldmatrix layouts ----------------
__global__ void fold_kernel(const float* __restrict__ comp_w,
                            const float* __restrict__ att_w,
                            const float* __restrict__ att_b) {
    int t = blockIdx.x * blockDim.x + threadIdx.x;
    if (t >= 64 * 9) return;
    int o = t / 9, tap = t % 9;
    int nb = o >> 3, no = o & 7;
    #pragma unroll 4
    for (int c = 0; c < 64; c++) {
        float w = comp_w[(o * 128 + c) * 9 + tap];
        __nv_bfloat16 h = __float2bfloat16(w);
        __nv_bfloat16 l = __float2bfloat16(w - __bfloat162float(h));
        int idx = ((tap * 8 + nb) * 64 + c) * 8 + no;
        g_wmh[idx] = h;
        g_wml[idx] = l;
    }
    float s0 = 0.f, s1 = 0.f, s2 = 0.f;
    #pragma unroll 4
    for (int c = 0; c < 64; c++) {
        float w = comp_w[(o * 128 + 64 + c) * 9 + tap];
        s0 += w * att_w[2 * c];
        s1 += w * att_w[2 * c + 1];
        s2 += w * att_b[c];
    }
    float sv[3] = {s0, s1, s2};
    #pragma unroll
    for (int j = 0; j < 3; j++) {
        int slot = tap * 3 + j;
        __nv_bfloat16 h = __float2bfloat16(sv[j]);
        __nv_bfloat16 l = __float2bfloat16(sv[j] - __bfloat162float(h));
        int idx = (nb * 32 + slot) * 8 + no;
        g_weh[idx] = h;
        g_wel[idx] = l;
    }
    if (tap == 0) {
        for (int s = 27; s < 32; s++) {
            int idx = (nb * 32 + s) * 8 + no;
            g_weh[idx] = __float2bfloat16(0.f);
            g_wel[idx] = __float2bfloat16(0.f);
        }
    }
}

// ---------------- gaussian splat: warp per point ----------------
__global__ void draw_kernel(const void* __restrict__ rcoors,
                            const float* __restrict__ rcs,
                            const float* __restrict__ gamma_p,
                            int N) {
    int p = blockIdx.x * 8 + (threadIdx.x >> 5);
    if (p >= N) return;
    int lane = threadIdx.x & 31;
    int is64 = g_coor64;
    int b, y, x;
    if (is64) {
        const long long* r8 = (const long long*)rcoors;
        b = (int)r8[p * 4 + 0]; y = (int)r8[p * 4 + 2]; x = (int)r8[p * 4 + 3];
    } else {
        const int* r4 = (const int*)rcoors;
        b = r4[p * 4 + 0]; y = r4[p * 4 + 2]; x = r4[p * 4 + 3];
    }
    float t = fmaxf(rcs[p], 0.0f);
    float gamma = *gamma_p;
    float r = floorf(gamma * t + 1.0f);
    float sigma = (2.0f * r + 1.0f) / 6.0f;
    float inv2s2 = 1.0f / (2.0f * sigma * sigma);
    int ri = (int)r;
    if (ri > HW) ri = HW;
    int side = 2 * ri + 1;
    int tot = side * side;
    const float EPS = 1.1920929e-7f;
    for (int idx = lane; idx < tot; idx += 32) {
        int dy = idx / side - ri;
        int dx = idx % side - ri;
        int py = y + dy, px = x + dx;
        if ((unsigned)py < HW && (unsigned)px < HW) {
            float d2 = (float)(dy * dy + dx * dx);
            float g = expf(-d2 * inv2s2);
            if (g >= EPS) {
                int off = b * (HW * HW) + py * HW + px;
                atomicMax((int*)&g_hm[off],  __float_as_int(g));
                atomicMax((int*)&g_hmf[off], __float_as_int(g * t));
            }
        }
    }
}

// ---------------- mma.sync conv, 16 warps ----------------
// CTA = one output row y, 128 px x 64 oc. Warp w: h=w>>3 (oc half), p=w&7 -> px [16p,16p+16) x 32 oc.
#define SM_WMH 0
#define SM_WML 73728
#define SM_WEH 147456
#define SM_WEL 151552
#define SM_RBH 155648
#define SM_RBL 174368
#define SM_EAH 193088
#define SM_EAL 203328
#define SMEM_TOTAL 213568
#define RB_STRIDE 144
#define EA_STRIDE 80
#define NTHREADS 512

__global__ void __launch_bounds__(NTHREADS, 1)
conv_mma_kernel(const float* __restrict__ lidar,
                const float* __restrict__ comp_b,
                float* __restrict__ out) {
    extern __shared__ char smc[];
    uint32_t sb = smem_u32(smc);
    const int tid  = threadIdx.x;
    const int wid  = tid >> 5;
    const int lane = tid & 31;
    const int y = blockIdx.x;
    const int b = blockIdx.y;

    // ---- copy weights to smem (uint4) ----
    {
        const uint4* s0 = (const uint4*)g_wmh; uint4* d0 = (uint4*)(smc + SM_WMH);
        const uint4* s1 = (const uint4*)g_wml; uint4* d1 = (uint4*)(smc + SM_WML);
        #pragma unroll 1
        for (int i = tid; i < 4608; i += NTHREADS) { d0[i] = s0[i]; d1[i] = s1[i]; }
        const uint4* s2 = (const uint4*)g_weh; uint4* d2 = (uint4*)(smc + SM_WEH);
        const uint4* s3 = (const uint4*)g_wel; uint4* d3 = (uint4*)(smc + SM_WEL);
        if (tid < 256) { d2[tid] = s2[tid]; d3[tid] = s3[tid]; }
    }

    // ---- zero guard rows 0 and 129 of row buffers ----
    if (tid < 72) {
        int r = (tid < 36) ? 0 : 129;
        int w = (tid < 36) ? tid : tid - 36;
        *(uint32_t*)(smc + SM_RBH + r * RB_STRIDE + w * 4) = 0;
        *(uint32_t*)(smc + SM_RBL + r * RB_STRIDE + w * 4) = 0;
    }

    // ---- build extra-channel A: [128 px][32 slots] hi/lo ----
    const float* hm_b  = g_hm  + b * HW * HW;
    const float* hmf_b = g_hmf + b * HW * HW;
    #pragma unroll 1
    for (int i = tid; i < 2048; i += NTHREADS) {
        int px = i & 127;
        int sp = i >> 7;                 // slot pair 0..15
        float v[2];
        #pragma unroll
        for (int u = 0; u < 2; u++) {
            int slot = sp * 2 + u;
            float val = 0.f;
            if (slot < 27) {
                int tap = slot / 3, j = slot - 3 * tap;
                int kyy = tap / 3, kxx = tap - 3 * kyy;
                int ry = y + kyy - 1, rx = px + kxx - 1;
                if ((unsigned)ry < HW && (unsigned)rx < HW) {
                    if (j == 0)      val = hm_b[ry * HW + rx];
                    else if (j == 1) val = hmf_b[ry * HW + rx];
                    else             val = 1.0f;
                }
            }
            v[u] = val;
        }
        uint32_t lp, hp = pack_hl(v[0], v[1], lp);
        *(uint32_t*)(smc + SM_EAH + px * EA_STRIDE + sp * 4) = hp;
        *(uint32_t*)(smc + SM_EAL + px * EA_STRIDE + sp * 4) = lp;
    }

    // ---- accumulators: 4 n-tiles of m16n8 ----
    float acc[4][4];
    #pragma unroll
    for (int t = 0; t < 4; t++)
        #pragma unroll
        for (int j = 0; j < 4; j++) acc[t][j] = 0.f;

    const int h   = wid >> 3;          // oc half
    const int px0 = (wid & 7) * 16;
    const uint32_t row_add = (lane & 7) + ((lane >> 3) & 1) * 8;  // 0..15
    const uint32_t a_half  = (lane >> 4) * 16;                    // 0 / 16B
    const uint32_t b_kidx  = lane & 15;
    const uint32_t b_nbadd = (lane >> 4);                         // 0 / 1

    const float* lid_b = lidar + (size_t)b * C_MID * HW * HW;

    for (int ky = 0; ky < 3; ky++) {
        int ry = y + ky - 1;
        int valid = ((unsigned)ry < HW);
        __syncthreads();
        if (valid) {
            const float* rp = lid_b + (size_t)ry * HW;
            #pragma unroll 1
            for (int i = tid; i < 4096; i += NTHREADS) {
                int px = i & 127;
                int cp = i >> 7;                 // channel pair 0..31
                float v0 = rp[(size_t)(2 * cp) * (HW * HW) + px];
                float v1 = rp[(size_t)(2 * cp + 1) * (HW * HW) + px];
                uint32_t lp, hp = pack_hl(v0, v1, lp);
                *(uint32_t*)(smc + SM_RBH + (px + 1) * RB_STRIDE + cp * 4) = hp;
                *(uint32_t*)(smc + SM_RBL + (px + 1) * RB_STRIDE + cp * 4) = lp;
            }
        }
        __syncthreads();
        if (!valid) continue;

        #pragma unroll
        for (int kx = 0; kx < 3; kx++) {
            int tap = ky * 3 + kx;
            uint32_t aH = sb + SM_RBH + (px0 + kx + row_add) * RB_STRIDE + a_half;
            uint32_t aL = aH + (SM_RBL - SM_RBH);
            uint32_t wB = sb + SM_WMH + (((tap * 8) + 4 * h + b_nbadd) * 64 + b_kidx) * 16;
            #pragma unroll
            for (int kc = 0; kc < 4; kc++) {
                uint32_t Ah[4], Al[4];
                ldsm_x4(aH + kc * 32, Ah[0], Ah[1], Ah[2], Ah[3]);
                ldsm_x4(aL + kc * 32, Al[0], Al[1], Al[2], Al[3]);
                #pragma unroll
                for (int nbp = 0; nbp < 2; nbp++) {
                    uint32_t bh0, bh1, bh2, bh3, bl0, bl1, bl2, bl3;
                    uint32_t boff = nbp * 2048 + kc * 256;
                    ldsm_x4_t(wB + boff, bh0, bh1, bh2, bh3);
                    ldsm_x4_t(wB + boff + (SM_WML - SM_WMH), bl0, bl1, bl2, bl3);
                    mma_bf16(acc[2 * nbp],     Ah, bh0, bh1);
                    mma_bf16(acc[2 * nbp + 1], Ah, bh2, bh3);
                    mma_bf16(acc[2 * nbp],     Ah, bl0, bl1);
                    mma_bf16(acc[2 * nbp + 1], Ah, bl2, bl3);
                    mma_bf16(acc[2 * nbp],     Al, bh0, bh1);
                    mma_bf16(acc[2 * nbp + 1], Al, bh2, bh3);
                }
            }
        }
    }

    // ---- extra channels: K = 32 (2 k-chunks) ----
    {
        uint32_t aH = sb + SM_EAH + (px0 + row_add) * EA_STRIDE + a_half;
        uint32_t aL = aH + (SM_EAL - SM_EAH);
        uint32_t wB = sb + SM_WEH + ((4 * h + b_nbadd) * 32 + b_kidx) * 16;
        #pragma unroll
        for (int kc = 0; kc < 2; kc++) {
            uint32_t Ah[4], Al[4];
            ldsm_x4(aH + kc * 32, Ah[0], Ah[1], Ah[2], Ah[3]);
            ldsm_x4(aL + kc * 32, Al[0], Al[1], Al[2], Al[3]);
            #pragma unroll
            for (int nbp = 0; nbp < 2; nbp++) {
                uint32_t bh0, bh1, bh2, bh3, bl0, bl1, bl2, bl3;
                uint32_t boff = nbp * 1024 + kc * 256;   // nb stride = 512B
                ldsm_x4_t(wB + boff, bh0, bh1, bh2, bh3);
                ldsm_x4_t(wB + boff + (SM_WEL - SM_WEH), bl0, bl1, bl2, bl3);
                mma_bf16(acc[2 * nbp],     Ah, bh0, bh1);
                mma_bf16(acc[2 * nbp + 1], Ah, bh2, bh3);
                mma_bf16(acc[2 * nbp],     Ah, bl0, bl1);
                mma_bf16(acc[2 * nbp + 1], Ah, bl2, bl3);
                mma_bf16(acc[2 * nbp],     Al, bh0, bh1);
                mma_bf16(acc[2 * nbp + 1], Al, bh2, bh3);
            }
        }
    }

    // ---- epilogue: D fragment -> NCHW + bias ----
    {
        int r0 = px0 + (lane >> 2);
        #pragma unroll
        for (int nt = 0; nt < 4; nt++) {
            int oc = h * 32 + nt * 8 + (lane & 3) * 2;
            float bv0 = comp_b[oc], bv1 = comp_b[oc + 1];
            float* o0 = out + (((size_t)b * 64 + oc) * HW + y) * HW;
            float* o1 = o0 + (size_t)HW * HW;
            o0[r0]     = acc[nt][0] + bv0;
            o1[r0]     = acc[nt][1] + bv1;
            o0[r0 + 8] = acc[nt][2] + bv0;
            o1[r0 + 8] = acc[nt][3] + bv1;
        }
    }
}

// ---------------- launch ----------------
extern "C" void kernel_launch(void* const* d_in, const int* in_sizes, int n_in,
                              void* d_out, int out_size) {
    const float* lidar  = (const float*)d_in[0];
    const void*  rcoors = d_in[2];
    const float* rcs    = (const float*)d_in[4];
    const float* gamma  = (const float*)d_in[5];
    const float* att_w  = (const float*)d_in[6];
    const float* att_b  = (const float*)d_in[7];
    const float* comp_w = (const float*)d_in[8];
    const float* comp_b = (const float*)d_in[9];
    float* out = (float*)d_out;

    int B = in_sizes[0] / (C_MID * HW * HW);
    if (B < 1) B = 1; if (B > MAXB) B = MAXB;
    int N = in_sizes[4];

    detect_kernel<<<1, 32>>>((const int*)rcoors);

    int nz = B * HW * HW;
    init_kernel<<<(nz + 255) / 256, 256>>>(nz);

    fold_kernel<<<3, 256>>>(comp_w, att_w, att_b);

    draw_kernel<<<(N + 7) / 8, 256>>>(rcoors, rcs, gamma, N);

    cudaFuncSetAttribute(conv_mma_kernel,
                         cudaFuncAttributeMaxDynamicSharedMemorySize, SMEM_TOTAL);
    dim3 grid(HW, B);
    conv_mma_kernel<<<grid, NTHREADS, SMEM_TOTAL>>>(lidar, comp_b, out);
}

// round 7
// speedup vs baseline: 2.7243x; 1.0195x over previous
#include <cuda_runtime.h>
#include <cuda_bf16.h>
#include <math.h>
#include <stdint.h>

#define HW 128
#define C_MID 64
#define MAXB 8

// ---------------- scratch (no allocs allowed) ----------------
__device__ float g_hm [MAXB * HW * HW];
__device__ float g_hmf[MAXB * HW * HW];
// main weight fragments, mma-B register layout:
// [tap(9)][npair(4)][kc(4)][hl(2)][lane(32)][reg(4)] uint32
__device__ __align__(16) uint32_t g_wfrag[9 * 4 * 4 * 2 * 32 * 4];
// extra-channel fragments: [npair(4)][kc(2)][hl(2)][lane(32)][reg(4)]
__device__ __align__(16) uint32_t g_efrag[4 * 2 * 2 * 32 * 4];
// extra-channel folded sums [oc(64)][slot(32)]
__device__ float g_esum[64 * 32];
__device__ int g_coor64;

// ---------------- helpers ----------------
__device__ __forceinline__ uint32_t smem_u32(const void* p) {
    uint32_t a;
    asm("{ .reg .u64 t; cvta.to.shared.u64 t, %1; cvt.u32.u64 %0, t; }" : "=r"(a) : "l"(p));
    return a;
}
__device__ __forceinline__ void ldsm_x4(uint32_t addr, uint32_t& r0, uint32_t& r1,
                                        uint32_t& r2, uint32_t& r3) {
    asm volatile("ldmatrix.sync.aligned.m8n8.x4.shared.b16 {%0,%1,%2,%3}, [%4];"
                 : "=r"(r0), "=r"(r1), "=r"(r2), "=r"(r3) : "r"(addr));
}
__device__ __forceinline__ void mma_bf16(float* d, const uint32_t* a,
                                         uint32_t b0, uint32_t b1) {
    asm volatile(
        "mma.sync.aligned.m16n8k16.row.col.f32.bf16.bf16.f32 "
        "{%0,%1,%2,%3},{%4,%5,%6,%7},{%8,%9},{%0,%1,%2,%3};"
        : "+f"(d[0]), "+f"(d[1]), "+f"(d[2]), "+f"(d[3])
        : "r"(a[0]), "r"(a[1]), "r"(a[2]), "r"(a[3]), "r"(b0), "r"(b1));
}
__device__ __forceinline__ uint32_t pack_hl(float v0, float v1, uint32_t& lo) {
    __nv_bfloat16 h0 = __float2bfloat16(v0);
    __nv_bfloat16 h1 = __float2bfloat16(v1);
    __nv_bfloat16 l0 = __float2bfloat16(v0 - __bfloat162float(h0));
    __nv_bfloat16 l1 = __float2bfloat16(v1 - __bfloat162float(h1));
    lo = (uint32_t)__bfloat16_as_ushort(l0) | ((uint32_t)__bfloat16_as_ushort(l1) << 16);
    return (uint32_t)__bfloat16_as_ushort(h0) | ((uint32_t)__bfloat16_as_ushort(h1) << 16);
}
__device__ __forceinline__ uint32_t pack_sel(float v0, float v1, int hl) {
    uint32_t lo, hi = pack_hl(v0, v1, lo);
    return hl ? lo : hi;
}

// ---------------- int64-vs-int32 rcoors detection ----------------
__global__ void detect_kernel(const int* rc_as_i32) {
    if (threadIdx.x == 0 && blockIdx.x == 0) {
        int all0 = 1;
        #pragma unroll 1
        for (int i = 1; i < 128; i += 2) all0 &= (rc_as_i32[i] == 0);
        g_coor64 = all0;
    }
}

// ---------------- zero heatmap buffers ----------------
__global__ void init_kernel(int n) {
    int i = blockIdx.x * blockDim.x + threadIdx.x;
    if (i < n) { g_hm[i] = 0.0f; g_hmf[i] = 0.0f; }
}

// ---------------- fold A: extra-channel sums ----------------
__global__ void fold_a_kernel(const float* __restrict__ comp_w,
                              const float* __restrict__ att_w,
                              const float* __restrict__ att_b) {
    int t = blockIdx.x * blockDim.x + threadIdx.x;
    if (t >= 64 * 9) return;
    int o = t / 9, tap = t % 9;
    float s0 = 0.f, s1 = 0.f, s2 = 0.f;
    #pragma unroll 4
    for (int c = 0; c < 64; c++) {
        float w = comp_w[(o * 128 + 64 + c) * 9 + tap];
        s0 += w * att_w[2 * c];
        s1 += w * att_w[2 * c + 1];
        s2 += w * att_b[c];
    }
    g_esum[o * 32 + tap * 3 + 0] = s0;
    g_esum[o * 32 + tap * 3 + 1] = s1;
    g_esum[o * 32 + tap * 3 + 2] = s2;
    if (tap == 0)
        for (int s = 27; s < 32; s++) g_esum[o * 32 + s] = 0.f;
}

// ---------------- fold B: build mma-order B fragments in gmem ----------------
// lane l of a B fragment (m16n8k16) holds B[k = 2*(l%4)+{0,1}][n = l/4],
// packed low = even k. reg m: nb = 2*npair + (m>>1), k-block = (m&1)*8.
__global__ void fold_b_kernel(const float* __restrict__ comp_w) {
    int t = blockIdx.x * blockDim.x + threadIdx.x;
    if (t < 9216) {               // main: [tap][npair][kc][hl][lane]
        int lane = t & 31;
        int r = t >> 5;
        int hl = r & 1;
        int kc = (r >> 1) & 3;
        int npair = (r >> 3) & 3;
        int tap = r >> 5;
        uint32_t v[4];
        #pragma unroll
        for (int m = 0; m < 4; m++) {
            int nb = 2 * npair + (m >> 1);
            int oc = nb * 8 + (lane >> 2);
            int k0 = kc * 16 + (m & 1) * 8 + 2 * (lane & 3);
            float w0 = comp_w[(oc * 128 + k0) * 9 + tap];
            float w1 = comp_w[(oc * 128 + k0 + 1) * 9 + tap];
            v[m] = pack_sel(w0, w1, hl);
        }
        *(uint4*)&g_wfrag[t * 4] = make_uint4(v[0], v[1], v[2], v[3]);
    } else if (t < 9216 + 512) {  // extra: [npair][kc][hl][lane]
        int e = t - 9216;
        int lane = e & 31;
        int r = e >> 5;
        int hl = r & 1;
        int kc = (r >> 1) & 1;
        int npair = r >> 2;
        uint32_t v[4];
        #pragma unroll
        for (int m = 0; m < 4; m++) {
            int nb = 2 * npair + (m >> 1);
            int oc = nb * 8 + (lane >> 2);
            int s0 = kc * 16 + (m & 1) * 8 + 2 * (lane & 3);
            float w0 = g_esum[oc * 32 + s0];
            float w1 = g_esum[oc * 32 + s0 + 1];
            v[m] = pack_sel(w0, w1, hl);
        }
        *(uint4*)&g_efrag[e * 4] = make_uint4(v[0], v[1], v[2], v[3]);
    }
}

// ---------------- gaussian splat: warp per point ----------------
__global__ void draw_kernel(const void* __restrict__ rcoors,
                            const float* __restrict__ rcs,
                            const float* __restrict__ gamma_p,
                            int N) {
    int p = blockIdx.x * 8 + (threadIdx.x >> 5);
    if (p >= N) return;
    int lane = threadIdx.x & 31;
    int is64 = g_coor64;
    int b, y, x;
    if (is64) {
        const long long* r8 = (const long long*)rcoors;
        b = (int)r8[p * 4 + 0]; y = (int)r8[p * 4 + 2]; x = (int)r8[p * 4 + 3];
    } else {
        const int* r4 = (const int*)rcoors;
        b = r4[p * 4 + 0]; y = r4[p * 4 + 2]; x = r4[p * 4 + 3];
    }
    float t = fmaxf(rcs[p], 0.0f);
    float gamma = *gamma_p;
    float r = floorf(gamma * t + 1.0f);
    float sigma = (2.0f * r + 1.0f) / 6.0f;
    float inv2s2 = 1.0f / (2.0f * sigma * sigma);
    int ri = (int)r;
    if (ri > HW) ri = HW;
    int side = 2 * ri + 1;
    int tot = side * side;
    const float EPS = 1.1920929e-7f;
    for (int idx = lane; idx < tot; idx += 32) {
        int dy = idx / side - ri;
        int dx = idx % side - ri;
        int py = y + dy, px = x + dx;
        if ((unsigned)py < HW && (unsigned)px < HW) {
            float d2 = (float)(dy * dy + dx * dx);
            float g = expf(-d2 * inv2s2);
            if (g >= EPS) {
                int off = b * (HW * HW) + py * HW + px;
                atomicMax((int*)&g_hm[off],  __float_as_int(g));
                atomicMax((int*)&g_hmf[off], __float_as_int(g * t));
            }
        }
    }
}

// ---------------- mma.sync conv, 16 warps, weights via LDG fragments ----------------
#define SM_RBH 0
#define SM_RBL 18720
#define SM_EAH 37440
#define SM_EAL 47680
#define SMEM_TOTAL 57920
#define RB_STRIDE 144
#define EA_STRIDE 80
#define NTHREADS 512

__global__ void __launch_bounds__(NTHREADS, 2)
conv_mma_kernel(const float* __restrict__ lidar,
                const float* __restrict__ comp_b,
                float* __restrict__ out) {
    extern __shared__ char smc[];
    uint32_t sb = smem_u32(smc);
    const int tid  = threadIdx.x;
    const int wid  = tid >> 5;
    const int lane = tid & 31;
    const int y = blockIdx.x;
    const int b = blockIdx.y;

    // ---- zero guard rows 0 and 129 of row buffers ----
    if (tid < 72) {
        int r = (tid < 36) ? 0 : 129;
        int w = (tid < 36) ? tid : tid - 36;
        *(uint32_t*)(smc + SM_RBH + r * RB_STRIDE + w * 4) = 0;
        *(uint32_t*)(smc + SM_RBL + r * RB_STRIDE + w * 4) = 0;
    }

    // ---- build extra-channel A: [128 px][32 slots] hi/lo ----
    const float* hm_b  = g_hm  + b * HW * HW;
    const float* hmf_b = g_hmf + b * HW * HW;
    #pragma unroll 1
    for (int i = tid; i < 2048; i += NTHREADS) {
        int px = i & 127;
        int sp = i >> 7;                 // slot pair 0..15
        float v[2];
        #pragma unroll
        for (int u = 0; u < 2; u++) {
            int slot = sp * 2 + u;
            float val = 0.f;
            if (slot < 27) {
                int tap = slot / 3, j = slot - 3 * tap;
                int kyy = tap / 3, kxx = tap - 3 * kyy;
                int ry = y + kyy - 1, rx = px + kxx - 1;
                if ((unsigned)ry < HW && (unsigned)rx < HW) {
                    if (j == 0)      val = hm_b[ry * HW + rx];
                    else if (j == 1) val = hmf_b[ry * HW + rx];
                    else             val = 1.0f;
                }
            }
            v[u] = val;
        }
        uint32_t lp, hp = pack_hl(v[0], v[1], lp);
        *(uint32_t*)(smc + SM_EAH + px * EA_STRIDE + sp * 4) = hp;
        *(uint32_t*)(smc + SM_EAL + px * EA_STRIDE + sp * 4) = lp;
    }

    // ---- accumulators: 4 n-tiles of m16n8 ----
    float acc[4][4];
    #pragma unroll
    for (int t = 0; t < 4; t++)
        #pragma unroll
        for (int j = 0; j < 4; j++) acc[t][j] = 0.f;

    const int h   = wid >> 3;          // oc half
    const int px0 = (wid & 7) * 16;
    const uint32_t row_add = (lane & 7) + ((lane >> 3) & 1) * 8;  // 0..15
    const uint32_t a_half  = (lane >> 4) * 16;                    // 0 / 16B

    // per-warp fragment base (uint4 index):
    // main idx = tap*1024 + (2h+nbp)*256 + kc*64 + hl*32 + lane
    const uint4* wf4 = (const uint4*)g_wfrag;
    const uint4* ef4 = (const uint4*)g_efrag;
    const int wbase = (2 * h) * 256 + lane;
    const int ebase = (2 * h) * 128 + lane;

    const float* lid_b = lidar + (size_t)b * C_MID * HW * HW;

    for (int ky = 0; ky < 3; ky++) {
        int ry = y + ky - 1;
        int valid = ((unsigned)ry < HW);
        __syncthreads();
        if (valid) {
            const float* rp = lid_b + (size_t)ry * HW;
            #pragma unroll 1
            for (int i = tid; i < 4096; i += NTHREADS) {
                int px = i & 127;
                int cp = i >> 7;                 // channel pair 0..31
                float v0 = rp[(size_t)(2 * cp) * (HW * HW) + px];
                float v1 = rp[(size_t)(2 * cp + 1) * (HW * HW) + px];
                uint32_t lp, hp = pack_hl(v0, v1, lp);
                *(uint32_t*)(smc + SM_RBH + (px + 1) * RB_STRIDE + cp * 4) = hp;
                *(uint32_t*)(smc + SM_RBL + (px + 1) * RB_STRIDE + cp * 4) = lp;
            }
        }
        __syncthreads();
        if (!valid) continue;

        #pragma unroll
        for (int kx = 0; kx < 3; kx++) {
            int tap = ky * 3 + kx;
            uint32_t aH = sb + SM_RBH + (px0 + kx + row_add) * RB_STRIDE + a_half;
            uint32_t aL = aH + (SM_RBL - SM_RBH);
            const uint4* wt = wf4 + tap * 1024 + wbase;
            #pragma unroll
            for (int kc = 0; kc < 4; kc++) {
                uint32_t Ah[4], Al[4];
                ldsm_x4(aH + kc * 32, Ah[0], Ah[1], Ah[2], Ah[3]);
                ldsm_x4(aL + kc * 32, Al[0], Al[1], Al[2], Al[3]);
                #pragma unroll
                for (int nbp = 0; nbp < 2; nbp++) {
                    uint4 bh = wt[nbp * 256 + kc * 64];
                    uint4 bl = wt[nbp * 256 + kc * 64 + 32];
                    mma_bf16(acc[2 * nbp],     Ah, bh.x, bh.y);
                    mma_bf16(acc[2 * nbp + 1], Ah, bh.z, bh.w);
                    mma_bf16(acc[2 * nbp],     Ah, bl.x, bl.y);
                    mma_bf16(acc[2 * nbp + 1], Ah, bl.z, bl.w);
                    mma_bf16(acc[2 * nbp],     Al, bh.x, bh.y);
                    mma_bf16(acc[2 * nbp + 1], Al, bh.z, bh.w);
                }
            }
        }
    }

    // ---- extra channels: K = 32 (2 k-chunks) ----
    {
        uint32_t aH = sb + SM_EAH + (px0 + row_add) * EA_STRIDE + a_half;
        uint32_t aL = aH + (SM_EAL - SM_EAH);
        #pragma unroll
        for (int kc = 0; kc < 2; kc++) {
            uint32_t Ah[4], Al[4];
            ldsm_x4(aH + kc * 32, Ah[0], Ah[1], Ah[2], Ah[3]);
            ldsm_x4(aL + kc * 32, Al[0], Al[1], Al[2], Al[3]);
            #pragma unroll
            for (int nbp = 0; nbp < 2; nbp++) {
                uint4 bh = ef4[ebase + nbp * 128 + kc * 64];
                uint4 bl = ef4[ebase + nbp * 128 + kc * 64 + 32];
                mma_bf16(acc[2 * nbp],     Ah, bh.x, bh.y);
                mma_bf16(acc[2 * nbp + 1], Ah, bh.z, bh.w);
                mma_bf16(acc[2 * nbp],     Ah, bl.x, bl.y);
                mma_bf16(acc[2 * nbp + 1], Ah, bl.z, bl.w);
                mma_bf16(acc[2 * nbp],     Al, bh.x, bh.y);
                mma_bf16(acc[2 * nbp + 1], Al, bh.z, bh.w);
            }
        }
    }

    // ---- epilogue: D fragment -> NCHW + bias ----
    {
        int r0 = px0 + (lane >> 2);
        #pragma unroll
        for (int nt = 0; nt < 4; nt++) {
            int oc = h * 32 + nt * 8 + (lane & 3) * 2;
            float bv0 = comp_b[oc], bv1 = comp_b[oc + 1];
            float* o0 = out + (((size_t)b * 64 + oc) * HW + y) * HW;
            float* o1 = o0 + (size_t)HW * HW;
            o0[r0]     = acc[nt][0] + bv0;
            o1[r0]     = acc[nt][1] + bv1;
            o0[r0 + 8] = acc[nt][2] + bv0;
            o1[r0 + 8] = acc[nt][3] + bv1;
        }
    }
}

// ---------------- launch ----------------
extern "C" void kernel_launch(void* const* d_in, const int* in_sizes, int n_in,
                              void* d_out, int out_size) {
    const float* lidar  = (const float*)d_in[0];
    const void*  rcoors = d_in[2];
    const float* rcs    = (const float*)d_in[4];
    const float* gamma  = (const float*)d_in[5];
    const float* att_w  = (const float*)d_in[6];
    const float* att_b  = (const float*)d_in[7];
    const float* comp_w = (const float*)d_in[8];
    const float* comp_b = (const float*)d_in[9];
    float* out = (float*)d_out;

    int B = in_sizes[0] / (C_MID * HW * HW);
    if (B < 1) B = 1; if (B > MAXB) B = MAXB;
    int N = in_sizes[4];

    detect_kernel<<<1, 32>>>((const int*)rcoors);                 // launch 1

    int nz = B * HW * HW;
    init_kernel<<<(nz + 255) / 256, 256>>>(nz);                   // launch 2

    fold_a_kernel<<<3, 256>>>(comp_w, att_w, att_b);              // launch 3
    fold_b_kernel<<<38, 256>>>(comp_w);                           // launch 4

    draw_kernel<<<(N + 7) / 8, 256>>>(rcoors, rcs, gamma, N);     // launch 5

    cudaFuncSetAttribute(conv_mma_kernel,
                         cudaFuncAttributeMaxDynamicSharedMemorySize, SMEM_TOTAL);
    dim3 grid(HW, B);
    conv_mma_kernel<<<grid, NTHREADS, SMEM_TOTAL>>>(lidar, comp_b, out);  // launch 6
}

// round 8
// speedup vs baseline: 3.9778x; 1.4601x over previous
#include <cuda_runtime.h>
#include <cuda_bf16.h>
#include <math.h>
#include <stdint.h>

#define HW 128
#define C_MID 64
#define MAXB 8

// ---------------- scratch (no allocs allowed) ----------------
__device__ float g_hm [MAXB * HW * HW];
__device__ float g_hmf[MAXB * HW * HW];
// main weight fragments, mma-B register layout:
// [tap(9)][npair(4)][kc(4)][hl(2)][lane(32)][reg(4)] uint32
__device__ __align__(16) uint32_t g_wfrag[9 * 4 * 4 * 2 * 32 * 4];
// extra-channel fragments: [npair(4)][kc(2)][hl(2)][lane(32)][reg(4)]
__device__ __align__(16) uint32_t g_efrag[4 * 2 * 2 * 32 * 4];
// extra-channel folded sums [oc(64)][slot(32)]
__device__ float g_esum[64 * 32];
__device__ int g_coor64;

// ---------------- helpers ----------------
__device__ __forceinline__ uint32_t smem_u32(const void* p) {
    uint32_t a;
    asm("{ .reg .u64 t; cvta.to.shared.u64 t, %1; cvt.u32.u64 %0, t; }" : "=r"(a) : "l"(p));
    return a;
}
__device__ __forceinline__ void ldsm_x4(uint32_t addr, uint32_t& r0, uint32_t& r1,
                                        uint32_t& r2, uint32_t& r3) {
    asm volatile("ldmatrix.sync.aligned.m8n8.x4.shared.b16 {%0,%1,%2,%3}, [%4];"
                 : "=r"(r0), "=r"(r1), "=r"(r2), "=r"(r3) : "r"(addr));
}
__device__ __forceinline__ void mma_bf16(float* d, const uint32_t* a,
                                         uint32_t b0, uint32_t b1) {
    asm volatile(
        "mma.sync.aligned.m16n8k16.row.col.f32.bf16.bf16.f32 "
        "{%0,%1,%2,%3},{%4,%5,%6,%7},{%8,%9},{%0,%1,%2,%3};"
        : "+f"(d[0]), "+f"(d[1]), "+f"(d[2]), "+f"(d[3])
        : "r"(a[0]), "r"(a[1]), "r"(a[2]), "r"(a[3]), "r"(b0), "r"(b1));
}
__device__ __forceinline__ uint32_t pack_hl(float v0, float v1, uint32_t& lo) {
    __nv_bfloat16 h0 = __float2bfloat16(v0);
    __nv_bfloat16 h1 = __float2bfloat16(v1);
    __nv_bfloat16 l0 = __float2bfloat16(v0 - __bfloat162float(h0));
    __nv_bfloat16 l1 = __float2bfloat16(v1 - __bfloat162float(h1));
    lo = (uint32_t)__bfloat16_as_ushort(l0) | ((uint32_t)__bfloat16_as_ushort(l1) << 16);
    return (uint32_t)__bfloat16_as_ushort(h0) | ((uint32_t)__bfloat16_as_ushort(h1) << 16);
}
__device__ __forceinline__ uint32_t pack_sel(float v0, float v1, int hl) {
    uint32_t lo, hi = pack_hl(v0, v1, lo);
    return hl ? lo : hi;
}

// ---------------- k1: detect + fold_a ----------------
__global__ void detect_fold_a_kernel(const int* __restrict__ rc_as_i32,
                                     const float* __restrict__ comp_w,
                                     const float* __restrict__ att_w,
                                     const float* __restrict__ att_b) {
    int t = blockIdx.x * blockDim.x + threadIdx.x;
    if (t == 0) {
        int all0 = 1;
        #pragma unroll 1
        for (int i = 1; i < 128; i += 2) all0 &= (rc_as_i32[i] == 0);
        g_coor64 = all0;
    }
    if (t >= 64 * 9) return;
    int o = t / 9, tap = t % 9;
    float s0 = 0.f, s1 = 0.f, s2 = 0.f;
    #pragma unroll 4
    for (int c = 0; c < 64; c++) {
        float w = comp_w[(o * 128 + 64 + c) * 9 + tap];
        s0 += w * att_w[2 * c];
        s1 += w * att_w[2 * c + 1];
        s2 += w * att_b[c];
    }
    g_esum[o * 32 + tap * 3 + 0] = s0;
    g_esum[o * 32 + tap * 3 + 1] = s1;
    g_esum[o * 32 + tap * 3 + 2] = s2;
    if (tap == 0)
        for (int s = 27; s < 32; s++) g_esum[o * 32 + s] = 0.f;
}

// ---------------- k2: init heatmaps + fold_b fragments ----------------
__global__ void init_fold_b_kernel(const float* __restrict__ comp_w,
                                   int nz, int init_blocks) {
    if ((int)blockIdx.x < init_blocks) {
        int i = blockIdx.x * blockDim.x + threadIdx.x;
        if (i < nz) { g_hm[i] = 0.0f; g_hmf[i] = 0.0f; }
        return;
    }
    int t = (blockIdx.x - init_blocks) * blockDim.x + threadIdx.x;
    if (t < 9216) {               // main: [tap][npair][kc][hl][lane]
        int lane = t & 31;
        int r = t >> 5;
        int hl = r & 1;
        int kc = (r >> 1) & 3;
        int npair = (r >> 3) & 3;
        int tap = r >> 5;
        uint32_t v[4];
        #pragma unroll
        for (int m = 0; m < 4; m++) {
            int nb = 2 * npair + (m >> 1);
            int oc = nb * 8 + (lane >> 2);
            int k0 = kc * 16 + (m & 1) * 8 + 2 * (lane & 3);
            float w0 = comp_w[(oc * 128 + k0) * 9 + tap];
            float w1 = comp_w[(oc * 128 + k0 + 1) * 9 + tap];
            v[m] = pack_sel(w0, w1, hl);
        }
        *(uint4*)&g_wfrag[t * 4] = make_uint4(v[0], v[1], v[2], v[3]);
    } else if (t < 9216 + 512) {  // extra: [npair][kc][hl][lane]
        int e = t - 9216;
        int lane = e & 31;
        int r = e >> 5;
        int hl = r & 1;
        int kc = (r >> 1) & 1;
        int npair = r >> 2;
        uint32_t v[4];
        #pragma unroll
        for (int m = 0; m < 4; m++) {
            int nb = 2 * npair + (m >> 1);
            int oc = nb * 8 + (lane >> 2);
            int s0 = kc * 16 + (m & 1) * 8 + 2 * (lane & 3);
            float w0 = g_esum[oc * 32 + s0];
            float w1 = g_esum[oc * 32 + s0 + 1];
            v[m] = pack_sel(w0, w1, hl);
        }
        *(uint4*)&g_efrag[e * 4] = make_uint4(v[0], v[1], v[2], v[3]);
    }
}

// ---------------- k3: gaussian splat, warp per point ----------------
__global__ void draw_kernel(const void* __restrict__ rcoors,
                            const float* __restrict__ rcs,
                            const float* __restrict__ gamma_p,
                            int N) {
    int p = blockIdx.x * 8 + (threadIdx.x >> 5);
    if (p >= N) return;
    int lane = threadIdx.x & 31;
    int is64 = g_coor64;
    int b, y, x;
    if (is64) {
        const long long* r8 = (const long long*)rcoors;
        b = (int)r8[p * 4 + 0]; y = (int)r8[p * 4 + 2]; x = (int)r8[p * 4 + 3];
    } else {
        const int* r4 = (const int*)rcoors;
        b = r4[p * 4 + 0]; y = r4[p * 4 + 2]; x = r4[p * 4 + 3];
    }
    float t = fmaxf(rcs[p], 0.0f);
    float gamma = *gamma_p;
    float r = floorf(gamma * t + 1.0f);
    float sigma = (2.0f * r + 1.0f) / 6.0f;
    float inv2s2 = 1.0f / (2.0f * sigma * sigma);
    int ri = (int)r;
    if (ri > HW) ri = HW;
    int side = 2 * ri + 1;
    int tot = side * side;
    const float EPS = 1.1920929e-7f;
    for (int idx = lane; idx < tot; idx += 32) {
        int dy = idx / side - ri;
        int dx = idx % side - ri;
        int py = y + dy, px = x + dx;
        if ((unsigned)py < HW && (unsigned)px < HW) {
            float d2 = (float)(dy * dy + dx * dx);
            float g = expf(-d2 * inv2s2);
            if (g >= EPS) {
                int off = b * (HW * HW) + py * HW + px;
                atomicMax((int*)&g_hm[off],  __float_as_int(g));
                atomicMax((int*)&g_hmf[off], __float_as_int(g * t));
            }
        }
    }
}

// ---------------- k4: mma.sync conv, double-buffered row pipeline ----------------
#define SM_RB0H 0
#define SM_RB0L 18720
#define SM_RB1H 37440
#define SM_RB1L 56160
#define SM_EAH  74880
#define SM_EAL  85120
#define SMEM_TOTAL 95360
#define RB_STRIDE 144
#define EA_STRIDE 80
#define NTHREADS 512

__global__ void __launch_bounds__(NTHREADS, 2)
conv_mma_kernel(const float* __restrict__ lidar,
                const float* __restrict__ comp_b,
                float* __restrict__ out) {
    extern __shared__ char smc[];
    uint32_t sb = smem_u32(smc);
    const int tid  = threadIdx.x;
    const int wid  = tid >> 5;
    const int lane = tid & 31;
    const int y = blockIdx.x;
    const int b = blockIdx.y;

    // ---- zero guard rows 0 / 129 of both row buffers (hi+lo) ----
    if (tid < 144) {
        int reg = tid / 36;                  // RB0H,RB0L,RB1H,RB1L
        int w = tid - reg * 36;
        uint32_t base = reg * 18720;
        *(uint32_t*)(smc + base + 0 * RB_STRIDE + w * 4)   = 0;
        *(uint32_t*)(smc + base + 129 * RB_STRIDE + w * 4) = 0;
    }

    const float* lid_b = lidar + (size_t)b * C_MID * HW * HW;
    const float* hm_b  = g_hm  + b * HW * HW;
    const float* hmf_b = g_hmf + b * HW * HW;

    // ---- prologue: build row (y-1) into buffer 0 ----
    if (y - 1 >= 0) {
        const float* rp = lid_b + (size_t)(y - 1) * HW;
        #pragma unroll
        for (int k = 0; k < 8; k++) {
            int i = tid + k * NTHREADS;
            int px = i & 127, cp = i >> 7;
            float v0 = rp[(size_t)(2 * cp) * (HW * HW) + px];
            float v1 = rp[(size_t)(2 * cp + 1) * (HW * HW) + px];
            uint32_t lp, hp = pack_hl(v0, v1, lp);
            *(uint32_t*)(smc + SM_RB0H + (px + 1) * RB_STRIDE + cp * 4) = hp;
            *(uint32_t*)(smc + SM_RB0L + (px + 1) * RB_STRIDE + cp * 4) = lp;
        }
    }

    // ---- build extra-channel A: [128 px][32 slots] hi/lo ----
    #pragma unroll 1
    for (int i = tid; i < 2048; i += NTHREADS) {
        int px = i & 127;
        int sp = i >> 7;
        float v[2];
        #pragma unroll
        for (int u = 0; u < 2; u++) {
            int slot = sp * 2 + u;
            float val = 0.f;
            if (slot < 27) {
                int tap = slot / 3, j = slot - 3 * tap;
                int kyy = tap / 3, kxx = tap - 3 * kyy;
                int ry = y + kyy - 1, rx = px + kxx - 1;
                if ((unsigned)ry < HW && (unsigned)rx < HW) {
                    if (j == 0)      val = hm_b[ry * HW + rx];
                    else if (j == 1) val = hmf_b[ry * HW + rx];
                    else             val = 1.0f;
                }
            }
            v[u] = val;
        }
        uint32_t lp, hp = pack_hl(v[0], v[1], lp);
        *(uint32_t*)(smc + SM_EAH + px * EA_STRIDE + sp * 4) = hp;
        *(uint32_t*)(smc + SM_EAL + px * EA_STRIDE + sp * 4) = lp;
    }
    __syncthreads();

    // ---- accumulators ----
    float acc[4][4];
    #pragma unroll
    for (int t = 0; t < 4; t++)
        #pragma unroll
        for (int j = 0; j < 4; j++) acc[t][j] = 0.f;

    const int h   = wid >> 3;
    const int px0 = (wid & 7) * 16;
    const uint32_t row_add = (lane & 7) + ((lane >> 3) & 1) * 8;
    const uint32_t a_half  = (lane >> 4) * 16;

    const uint4* wf4 = (const uint4*)g_wfrag;
    const uint4* ef4 = (const uint4*)g_efrag;
    const int wbase = (2 * h) * 256 + lane;
    const int ebase = (2 * h) * 128 + lane;

    for (int ky = 0; ky < 3; ky++) {
        int ry = y + ky - 1;
        int vcur = ((unsigned)ry < HW);

        // prefetch next row into registers
        float pf0[8], pf1[8];
        int ryn = y + ky;
        int vnext = (ky < 2) && (ryn < HW);
        if (vnext) {
            const float* rp = lid_b + (size_t)ryn * HW;
            #pragma unroll
            for (int k = 0; k < 8; k++) {
                int i = tid + k * NTHREADS;
                int px = i & 127, cp = i >> 7;
                pf0[k] = rp[(size_t)(2 * cp) * (HW * HW) + px];
                pf1[k] = rp[(size_t)(2 * cp + 1) * (HW * HW) + px];
            }
        }

        if (vcur) {
            uint32_t bufH = (ky & 1) ? SM_RB1H : SM_RB0H;
            #pragma unroll
            for (int kx = 0; kx < 3; kx++) {
                int tap = ky * 3 + kx;
                uint32_t aH = sb + bufH + (px0 + kx + row_add) * RB_STRIDE + a_half;
                uint32_t aL = aH + 18720;
                const uint4* wt = wf4 + tap * 1024 + wbase;
                #pragma unroll
                for (int kc = 0; kc < 4; kc++) {
                    uint32_t Ah[4], Al[4];
                    ldsm_x4(aH + kc * 32, Ah[0], Ah[1], Ah[2], Ah[3]);
                    ldsm_x4(aL + kc * 32, Al[0], Al[1], Al[2], Al[3]);
                    #pragma unroll
                    for (int nbp = 0; nbp < 2; nbp++) {
                        uint4 bh = wt[nbp * 256 + kc * 64];
                        uint4 bl = wt[nbp * 256 + kc * 64 + 32];
                        mma_bf16(acc[2 * nbp],     Ah, bh.x, bh.y);
                        mma_bf16(acc[2 * nbp + 1], Ah, bh.z, bh.w);
                        mma_bf16(acc[2 * nbp],     Ah, bl.x, bl.y);
                        mma_bf16(acc[2 * nbp + 1], Ah, bl.z, bl.w);
                        mma_bf16(acc[2 * nbp],     Al, bh.x, bh.y);
                        mma_bf16(acc[2 * nbp + 1], Al, bh.z, bh.w);
                    }
                }
            }
        }

        if (ky < 2) {
            if (vnext) {
                uint32_t dH = ((ky + 1) & 1) ? SM_RB1H : SM_RB0H;
                uint32_t dL = dH + 18720;
                #pragma unroll
                for (int k = 0; k < 8; k++) {
                    int i = tid + k * NTHREADS;
                    int px = i & 127, cp = i >> 7;
                    uint32_t lp, hp = pack_hl(pf0[k], pf1[k], lp);
                    *(uint32_t*)(smc + dH + (px + 1) * RB_STRIDE + cp * 4) = hp;
                    *(uint32_t*)(smc + dL + (px + 1) * RB_STRIDE + cp * 4) = lp;
                }
            }
            __syncthreads();
        }
    }

    // ---- extra channels: K = 32 ----
    {
        uint32_t aH = sb + SM_EAH + (px0 + row_add) * EA_STRIDE + a_half;
        uint32_t aL = aH + (SM_EAL - SM_EAH);
        #pragma unroll
        for (int kc = 0; kc < 2; kc++) {
            uint32_t Ah[4], Al[4];
            ldsm_x4(aH + kc * 32, Ah[0], Ah[1], Ah[2], Ah[3]);
            ldsm_x4(aL + kc * 32, Al[0], Al[1], Al[2], Al[3]);
            #pragma unroll
            for (int nbp = 0; nbp < 2; nbp++) {
                uint4 bh = ef4[ebase + nbp * 128 + kc * 64];
                uint4 bl = ef4[ebase + nbp * 128 + kc * 64 + 32];
                mma_bf16(acc[2 * nbp],     Ah, bh.x, bh.y);
                mma_bf16(acc[2 * nbp + 1], Ah, bh.z, bh.w);
                mma_bf16(acc[2 * nbp],     Ah, bl.x, bl.y);
                mma_bf16(acc[2 * nbp + 1], Ah, bl.z, bl.w);
                mma_bf16(acc[2 * nbp],     Al, bh.x, bh.y);
                mma_bf16(acc[2 * nbp + 1], Al, bh.z, bh.w);
            }
        }
    }

    // ---- epilogue ----
    {
        int r0 = px0 + (lane >> 2);
        #pragma unroll
        for (int nt = 0; nt < 4; nt++) {
            int oc = h * 32 + nt * 8 + (lane & 3) * 2;
            float bv0 = comp_b[oc], bv1 = comp_b[oc + 1];
            float* o0 = out + (((size_t)b * 64 + oc) * HW + y) * HW;
            float* o1 = o0 + (size_t)HW * HW;
            o0[r0]     = acc[nt][0] + bv0;
            o1[r0]     = acc[nt][1] + bv1;
            o0[r0 + 8] = acc[nt][2] + bv0;
            o1[r0 + 8] = acc[nt][3] + bv1;
        }
    }
}

// ---------------- launch ----------------
extern "C" void kernel_launch(void* const* d_in, const int* in_sizes, int n_in,
                              void* d_out, int out_size) {
    const float* lidar  = (const float*)d_in[0];
    const void*  rcoors = d_in[2];
    const float* rcs    = (const float*)d_in[4];
    const float* gamma  = (const float*)d_in[5];
    const float* att_w  = (const float*)d_in[6];
    const float* att_b  = (const float*)d_in[7];
    const float* comp_w = (const float*)d_in[8];
    const float* comp_b = (const float*)d_in[9];
    float* out = (float*)d_out;

    int B = in_sizes[0] / (C_MID * HW * HW);
    if (B < 1) B = 1; if (B > MAXB) B = MAXB;
    int N = in_sizes[4];

    // k1: detect + fold_a
    detect_fold_a_kernel<<<3, 256>>>((const int*)rcoors, comp_w, att_w, att_b);

    // k2: init heatmaps + fold_b
    int nz = B * HW * HW;
    int init_blocks = (nz + 255) / 256;
    init_fold_b_kernel<<<init_blocks + 38, 256>>>(comp_w, nz, init_blocks);

    // k3: draw
    draw_kernel<<<(N + 7) / 8, 256>>>(rcoors, rcs, gamma, N);

    // k4: conv (profiled launch)
    cudaFuncSetAttribute(conv_mma_kernel,
                         cudaFuncAttributeMaxDynamicSharedMemorySize, SMEM_TOTAL);
    dim3 grid(HW, B);
    conv_mma_kernel<<<grid, NTHREADS, SMEM_TOTAL>>>(lidar, comp_b, out);
}

// round 13
// speedup vs baseline: 4.2595x; 1.0708x over previous
#include <cuda_runtime.h>
#include <cuda_bf16.h>
#include <math.h>
#include <stdint.h>

#define HW 128
#define C_MID 64
#define MAXB 8

// ---------------- scratch (no allocs allowed) ----------------
__device__ float g_hm [MAXB * HW * HW];
__device__ float g_hmf[MAXB * HW * HW];
// main weight fragments, mma-B register layout:
// [tap(9)][npair(4)][kc(4)][hl(2)][lane(32)][reg(4)] uint32
__device__ __align__(16) uint32_t g_wfrag[9 * 4 * 4 * 2 * 32 * 4];
// extra-channel fragments: [npair(4)][kc(2)][hl(2)][lane(32)][reg(4)]
__device__ __align__(16) uint32_t g_efrag[4 * 2 * 2 * 32 * 4];
// extra-channel folded sums [oc(64)][slot(32)]
__device__ float g_esum[64 * 32];
__device__ int g_coor64;

// ---------------- helpers ----------------
__device__ __forceinline__ uint32_t smem_u32(const void* p) {
    uint32_t a;
    asm("{ .reg .u64 t; cvta.to.shared.u64 t, %1; cvt.u32.u64 %0, t; }" : "=r"(a) : "l"(p));
    return a;
}
__device__ __forceinline__ void ldsm_x4(uint32_t addr, uint32_t& r0, uint32_t& r1,
                                        uint32_t& r2, uint32_t& r3) {
    asm volatile("ldmatrix.sync.aligned.m8n8.x4.shared.b16 {%0,%1,%2,%3}, [%4];"
                 : "=r"(r0), "=r"(r1), "=r"(r2), "=r"(r3) : "r"(addr));
}
__device__ __forceinline__ void mma_bf16(float* d, const uint32_t* a,
                                         uint32_t b0, uint32_t b1) {
    asm volatile(
        "mma.sync.aligned.m16n8k16.row.col.f32.bf16.bf16.f32 "
        "{%0,%1,%2,%3},{%4,%5,%6,%7},{%8,%9},{%0,%1,%2,%3};"
        : "+f"(d[0]), "+f"(d[1]), "+f"(d[2]), "+f"(d[3])
        : "r"(a[0]), "r"(a[1]), "r"(a[2]), "r"(a[3]), "r"(b0), "r"(b1));
}
__device__ __forceinline__ uint32_t pack_hl(float v0, float v1, uint32_t& lo) {
    __nv_bfloat16 h0 = __float2bfloat16(v0);
    __nv_bfloat16 h1 = __float2bfloat16(v1);
    __nv_bfloat16 l0 = __float2bfloat16(v0 - __bfloat162float(h0));
    __nv_bfloat16 l1 = __float2bfloat16(v1 - __bfloat162float(h1));
    lo = (uint32_t)__bfloat16_as_ushort(l0) | ((uint32_t)__bfloat16_as_ushort(l1) << 16);
    return (uint32_t)__bfloat16_as_ushort(h0) | ((uint32_t)__bfloat16_as_ushort(h1) << 16);
}
__device__ __forceinline__ uint32_t pack_sel(float v0, float v1, int hl) {
    uint32_t lo, hi = pack_hl(v0, v1, lo);
    return hl ? lo : hi;
}

// ---------------- k1: detect + fold_a ----------------
__global__ void detect_fold_a_kernel(const int* __restrict__ rc_as_i32,
                                     const float* __restrict__ comp_w,
                                     const float* __restrict__ att_w,
                                     const float* __restrict__ att_b) {
    int t = blockIdx.x * blockDim.x + threadIdx.x;
    if (t == 0) {
        int all0 = 1;
        #pragma unroll 1
        for (int i = 1; i < 128; i += 2) all0 &= (rc_as_i32[i] == 0);
        g_coor64 = all0;
    }
    if (t >= 64 * 9) return;
    int o = t / 9, tap = t % 9;
    float s0 = 0.f, s1 = 0.f, s2 = 0.f;
    #pragma unroll 4
    for (int c = 0; c < 64; c++) {
        float w = comp_w[(o * 128 + 64 + c) * 9 + tap];
        s0 += w * att_w[2 * c];
        s1 += w * att_w[2 * c + 1];
        s2 += w * att_b[c];
    }
    g_esum[o * 32 + tap * 3 + 0] = s0;
    g_esum[o * 32 + tap * 3 + 1] = s1;
    g_esum[o * 32 + tap * 3 + 2] = s2;
    if (tap == 0)
        for (int s = 27; s < 32; s++) g_esum[o * 32 + s] = 0.f;
}

// ---------------- k2: init heatmaps + fold_b fragments ----------------
__global__ void init_fold_b_kernel(const float* __restrict__ comp_w,
                                   int nz, int init_blocks) {
    if ((int)blockIdx.x < init_blocks) {
        int i = blockIdx.x * blockDim.x + threadIdx.x;
        if (i < nz) { g_hm[i] = 0.0f; g_hmf[i] = 0.0f; }
        return;
    }
    int t = (blockIdx.x - init_blocks) * blockDim.x + threadIdx.x;
    if (t < 9216) {               // main: [tap][npair][kc][hl][lane]
        int lane = t & 31;
        int r = t >> 5;
        int hl = r & 1;
        int kc = (r >> 1) & 3;
        int npair = (r >> 3) & 3;
        int tap = r >> 5;
        uint32_t v[4];
        #pragma unroll
        for (int m = 0; m < 4; m++) {
            int nb = 2 * npair + (m >> 1);
            int oc = nb * 8 + (lane >> 2);
            int k0 = kc * 16 + (m & 1) * 8 + 2 * (lane & 3);
            float w0 = comp_w[(oc * 128 + k0) * 9 + tap];
            float w1 = comp_w[(oc * 128 + k0 + 1) * 9 + tap];
            v[m] = pack_sel(w0, w1, hl);
        }
        *(uint4*)&g_wfrag[t * 4] = make_uint4(v[0], v[1], v[2], v[3]);
    } else if (t < 9216 + 512) {  // extra: [npair][kc][hl][lane]
        int e = t - 9216;
        int lane = e & 31;
        int r = e >> 5;
        int hl = r & 1;
        int kc = (r >> 1) & 1;
        int npair = r >> 2;
        uint32_t v[4];
        #pragma unroll
        for (int m = 0; m < 4; m++) {
            int nb = 2 * npair + (m >> 1);
            int oc = nb * 8 + (lane >> 2);
            int s0 = kc * 16 + (m & 1) * 8 + 2 * (lane & 3);
            float w0 = g_esum[oc * 32 + s0];
            float w1 = g_esum[oc * 32 + s0 + 1];
            v[m] = pack_sel(w0, w1, hl);
        }
        *(uint4*)&g_efrag[e * 4] = make_uint4(v[0], v[1], v[2], v[3]);
    }
}

// ---------------- k3: gaussian splat, warp per point ----------------
__global__ void draw_kernel(const void* __restrict__ rcoors,
                            const float* __restrict__ rcs,
                            const float* __restrict__ gamma_p,
                            int N) {
    int p = blockIdx.x * 8 + (threadIdx.x >> 5);
    if (p >= N) return;
    int lane = threadIdx.x & 31;
    int is64 = g_coor64;
    int b, y, x;
    if (is64) {
        const long long* r8 = (const long long*)rcoors;
        b = (int)r8[p * 4 + 0]; y = (int)r8[p * 4 + 2]; x = (int)r8[p * 4 + 3];
    } else {
        const int* r4 = (const int*)rcoors;
        b = r4[p * 4 + 0]; y = r4[p * 4 + 2]; x = r4[p * 4 + 3];
    }
    float t = fmaxf(rcs[p], 0.0f);
    float gamma = *gamma_p;
    float r = floorf(gamma * t + 1.0f);
    float sigma = (2.0f * r + 1.0f) / 6.0f;
    float inv2s2 = 1.0f / (2.0f * sigma * sigma);
    int ri = (int)r;
    if (ri > HW) ri = HW;
    int side = 2 * ri + 1;
    int tot = side * side;
    const float EPS = 1.1920929e-7f;
    for (int idx = lane; idx < tot; idx += 32) {
        int dy = idx / side - ri;
        int dx = idx % side - ri;
        int py = y + dy, px = x + dx;
        if ((unsigned)py < HW && (unsigned)px < HW) {
            float d2 = (float)(dy * dy + dx * dx);
            float g = expf(-d2 * inv2s2);
            if (g >= EPS) {
                int off = b * (HW * HW) + py * HW + px;
                atomicMax((int*)&g_hm[off],  __float_as_int(g));
                atomicMax((int*)&g_hmf[off], __float_as_int(g * t));
            }
        }
    }
}

// ---------------- k4: mma.sync conv, 8 fat warps (32px x 32oc) ----------------
#define SM_RB0H 0
#define SM_RB0L 18720
#define SM_RB1H 37440
#define SM_RB1L 56160
#define SM_EAH  74880
#define SM_EAL  85120
#define SMEM_TOTAL 95360
#define RB_STRIDE 144
#define EA_STRIDE 80
#define NTHREADS 256

__global__ void __launch_bounds__(NTHREADS, 2)
conv_mma_kernel(const float* __restrict__ lidar,
                const float* __restrict__ comp_b,
                float* __restrict__ out) {
    extern __shared__ char smc[];
    uint32_t sb = smem_u32(smc);
    const int tid  = threadIdx.x;
    const int wid  = tid >> 5;
    const int lane = tid & 31;
    const int y = blockIdx.x;
    const int b = blockIdx.y;

    // ---- zero guard rows 0 / 129 of both row buffers (hi+lo) ----
    if (tid < 144) {
        int reg = tid / 36;                  // RB0H,RB0L,RB1H,RB1L
        int w = tid - reg * 36;
        uint32_t base = reg * 18720;
        *(uint32_t*)(smc + base + 0 * RB_STRIDE + w * 4)   = 0;
        *(uint32_t*)(smc + base + 129 * RB_STRIDE + w * 4) = 0;
    }

    const float* lid_b = lidar + (size_t)b * C_MID * HW * HW;
    const float* hm_b  = g_hm  + b * HW * HW;
    const float* hmf_b = g_hmf + b * HW * HW;

    // ---- prologue: build row (y-1) into buffer 0 ----
    if (y - 1 >= 0) {
        const float* rp = lid_b + (size_t)(y - 1) * HW;
        #pragma unroll
        for (int k = 0; k < 16; k++) {
            int i = tid + k * NTHREADS;
            int px = i & 127, cp = i >> 7;
            float v0 = rp[(size_t)(2 * cp) * (HW * HW) + px];
            float v1 = rp[(size_t)(2 * cp + 1) * (HW * HW) + px];
            uint32_t lp, hp = pack_hl(v0, v1, lp);
            *(uint32_t*)(smc + SM_RB0H + (px + 1) * RB_STRIDE + cp * 4) = hp;
            *(uint32_t*)(smc + SM_RB0L + (px + 1) * RB_STRIDE + cp * 4) = lp;
        }
    }

    // ---- build extra-channel A: [128 px][32 slots] hi/lo ----
    #pragma unroll 1
    for (int i = tid; i < 2048; i += NTHREADS) {
        int px = i & 127;
        int sp = i >> 7;
        float v[2];
        #pragma unroll
        for (int u = 0; u < 2; u++) {
            int slot = sp * 2 + u;
            float val = 0.f;
            if (slot < 27) {
                int tap = slot / 3, j = slot - 3 * tap;
                int kyy = tap / 3, kxx = tap - 3 * kyy;
                int ry = y + kyy - 1, rx = px + kxx - 1;
                if ((unsigned)ry < HW && (unsigned)rx < HW) {
                    if (j == 0)      val = hm_b[ry * HW + rx];
                    else if (j == 1) val = hmf_b[ry * HW + rx];
                    else             val = 1.0f;
                }
            }
            v[u] = val;
        }
        uint32_t lp, hp = pack_hl(v[0], v[1], lp);
        *(uint32_t*)(smc + SM_EAH + px * EA_STRIDE + sp * 4) = hp;
        *(uint32_t*)(smc + SM_EAL + px * EA_STRIDE + sp * 4) = lp;
    }
    __syncthreads();

    // ---- accumulators: 2 m-tiles x 4 n-tiles ----
    float acc[2][4][4];
    #pragma unroll
    for (int mt = 0; mt < 2; mt++)
        #pragma unroll
        for (int t = 0; t < 4; t++)
            #pragma unroll
            for (int j = 0; j < 4; j++) acc[mt][t][j] = 0.f;

    const int h   = wid & 1;           // oc half
    const int px0 = (wid >> 1) * 32;   // 32-px group
    const uint32_t row_add = (lane & 7) + ((lane >> 3) & 1) * 8;
    const uint32_t a_half  = (lane >> 4) * 16;

    const uint4* wf4 = (const uint4*)g_wfrag;
    const uint4* ef4 = (const uint4*)g_efrag;
    const int wbase = (2 * h) * 256 + lane;
    const int ebase = (2 * h) * 128 + lane;

    for (int ky = 0; ky < 3; ky++) {
        int ry = y + ky - 1;
        int vcur = ((unsigned)ry < HW);

        // prefetch next row into registers
        float pf0[16], pf1[16];
        int ryn = y + ky;
        int vnext = (ky < 2) && (ryn < HW);
        if (vnext) {
            const float* rp = lid_b + (size_t)ryn * HW;
            #pragma unroll
            for (int k = 0; k < 16; k++) {
                int i = tid + k * NTHREADS;
                int px = i & 127, cp = i >> 7;
                pf0[k] = rp[(size_t)(2 * cp) * (HW * HW) + px];
                pf1[k] = rp[(size_t)(2 * cp + 1) * (HW * HW) + px];
            }
        }

        if (vcur) {
            uint32_t bufH = (ky & 1) ? SM_RB1H : SM_RB0H;
            #pragma unroll
            for (int kx = 0; kx < 3; kx++) {
                int tap = ky * 3 + kx;
                uint32_t a0 = sb + bufH + (px0 + kx + row_add) * RB_STRIDE + a_half;
                const uint4* wt = wf4 + tap * 1024 + wbase;
                #pragma unroll
                for (int kc = 0; kc < 4; kc++) {
                    uint32_t Ah[2][4], Al[2][4];
                    #pragma unroll
                    for (int mt = 0; mt < 2; mt++) {
                        uint32_t aH = a0 + mt * (16 * RB_STRIDE) + kc * 32;
                        ldsm_x4(aH, Ah[mt][0], Ah[mt][1], Ah[mt][2], Ah[mt][3]);
                        ldsm_x4(aH + 18720, Al[mt][0], Al[mt][1], Al[mt][2], Al[mt][3]);
                    }
                    #pragma unroll
                    for (int nbp = 0; nbp < 2; nbp++) {
                        uint4 bh = wt[nbp * 256 + kc * 64];
                        uint4 bl = wt[nbp * 256 + kc * 64 + 32];
                        #pragma unroll
                        for (int mt = 0; mt < 2; mt++) {
                            mma_bf16(acc[mt][2 * nbp],     Ah[mt], bh.x, bh.y);
                            mma_bf16(acc[mt][2 * nbp + 1], Ah[mt], bh.z, bh.w);
                            mma_bf16(acc[mt][2 * nbp],     Ah[mt], bl.x, bl.y);
                            mma_bf16(acc[mt][2 * nbp + 1], Ah[mt], bl.z, bl.w);
                            mma_bf16(acc[mt][2 * nbp],     Al[mt], bh.x, bh.y);
                            mma_bf16(acc[mt][2 * nbp + 1], Al[mt], bh.z, bh.w);
                        }
                    }
                }
            }
        }

        if (ky < 2) {
            if (vnext) {
                uint32_t dH = ((ky + 1) & 1) ? SM_RB1H : SM_RB0H;
                uint32_t dL = dH + 18720;
                #pragma unroll
                for (int k = 0; k < 16; k++) {
                    int i = tid + k * NTHREADS;
                    int px = i & 127, cp = i >> 7;
                    uint32_t lp, hp = pack_hl(pf0[k], pf1[k], lp);
                    *(uint32_t*)(smc + dH + (px + 1) * RB_STRIDE + cp * 4) = hp;
                    *(uint32_t*)(smc + dL + (px + 1) * RB_STRIDE + cp * 4) = lp;
                }
            }
            __syncthreads();
        }
    }

    // ---- extra channels: K = 32 ----
    {
        uint32_t a0 = sb + SM_EAH + (px0 + row_add) * EA_STRIDE + a_half;
        #pragma unroll
        for (int kc = 0; kc < 2; kc++) {
            uint32_t Ah[2][4], Al[2][4];
            #pragma unroll
            for (int mt = 0; mt < 2; mt++) {
                uint32_t aH = a0 + mt * (16 * EA_STRIDE) + kc * 32;
                ldsm_x4(aH, Ah[mt][0], Ah[mt][1], Ah[mt][2], Ah[mt][3]);
                ldsm_x4(aH + (SM_EAL - SM_EAH), Al[mt][0], Al[mt][1], Al[mt][2], Al[mt][3]);
            }
            #pragma unroll
            for (int nbp = 0; nbp < 2; nbp++) {
                uint4 bh = ef4[ebase + nbp * 128 + kc * 64];
                uint4 bl = ef4[ebase + nbp * 128 + kc * 64 + 32];
                #pragma unroll
                for (int mt = 0; mt < 2; mt++) {
                    mma_bf16(acc[mt][2 * nbp],     Ah[mt], bh.x, bh.y);
                    mma_bf16(acc[mt][2 * nbp + 1], Ah[mt], bh.z, bh.w);
                    mma_bf16(acc[mt][2 * nbp],     Ah[mt], bl.x, bl.y);
                    mma_bf16(acc[mt][2 * nbp + 1], Ah[mt], bl.z, bl.w);
                    mma_bf16(acc[mt][2 * nbp],     Al[mt], bh.x, bh.y);
                    mma_bf16(acc[mt][2 * nbp + 1], Al[mt], bh.z, bh.w);
                }
            }
        }
    }

    // ---- epilogue ----
    {
        #pragma unroll
        for (int mt = 0; mt < 2; mt++) {
            int r0 = px0 + mt * 16 + (lane >> 2);
            #pragma unroll
            for (int nt = 0; nt < 4; nt++) {
                int oc = h * 32 + nt * 8 + (lane & 3) * 2;
                float bv0 = comp_b[oc], bv1 = comp_b[oc + 1];
                float* o0 = out + (((size_t)b * 64 + oc) * HW + y) * HW;
                float* o1 = o0 + (size_t)HW * HW;
                o0[r0]     = acc[mt][nt][0] + bv0;
                o1[r0]     = acc[mt][nt][1] + bv1;
                o0[r0 + 8] = acc[mt][nt][2] + bv0;
                o1[r0 + 8] = acc[mt][nt][3] + bv1;
            }
        }
    }
}

// ---------------- launch ----------------
extern "C" void kernel_launch(void* const* d_in, const int* in_sizes, int n_in,
                              void* d_out, int out_size) {
    const float* lidar  = (const float*)d_in[0];
    const void*  rcoors = d_in[2];
    const float* rcs    = (const float*)d_in[4];
    const float* gamma  = (const float*)d_in[5];
    const float* att_w  = (const float*)d_in[6];
    const float* att_b  = (const float*)d_in[7];
    const float* comp_w = (const float*)d_in[8];
    const float* comp_b = (const float*)d_in[9];
    float* out = (float*)d_out;

    int B = in_sizes[0] / (C_MID * HW * HW);
    if (B < 1) B = 1; if (B > MAXB) B = MAXB;
    int N = in_sizes[4];

    // k1: detect + fold_a
    detect_fold_a_kernel<<<3, 256>>>((const int*)rcoors, comp_w, att_w, att_b);

    // k2: init heatmaps + fold_b
    int nz = B * HW * HW;
    int init_blocks = (nz + 255) / 256;
    init_fold_b_kernel<<<init_blocks + 38, 256>>>(comp_w, nz, init_blocks);

    // k3: draw
    draw_kernel<<<(N + 7) / 8, 256>>>(rcoors, rcs, gamma, N);

    // k4: conv (profiled launch)
    cudaFuncSetAttribute(conv_mma_kernel,
                         cudaFuncAttributeMaxDynamicSharedMemorySize, SMEM_TOTAL);
    dim3 grid(HW, B);
    conv_mma_kernel<<<grid, NTHREADS, SMEM_TOTAL>>>(lidar, comp_b, out);
}